// round 8
// baseline (speedup 1.0000x reference)
#include <cuda_runtime.h>
#include <cstdint>

#define HIDDEN 1024
#define NCOLS 1858
#define NROWS_PM 4288
#define MAXB 2048
#define NSEG 16

// ---------------- scratch (device globals: allocation-free) ----------------
__device__ float g_HS[(size_t)MAXB * 64 * HIDDEN];  // HS tf32-rounded
__device__ float g_M[HIDDEN * HIDDEN];              // g_M[n][k] = M[k][n] (tf32-rounded)
__device__ float g_Weff[3 * HIDDEN];
__device__ float g_PO[MAXB * 24];
__device__ int   g_cnt[NCOLS];
__device__ int   g_rows[NCOLS * 16];
__device__ int   g_cntS[NSEG * NCOLS];
__device__ int   g_rowsS[NSEG * NCOLS * 8];

// ---------------- PTX helpers (arch-agnostic: sm_80+ only) -----------------
__device__ __forceinline__ uint32_t smem_u32(const void* p) {
    uint32_t a;
    asm("{ .reg .u64 t; cvta.to.shared.u64 t, %1; cvt.u32.u64 %0, t; }" : "=r"(a) : "l"(p));
    return a;
}
__device__ __forceinline__ void cp_async16(uint32_t s, const void* g) {
    asm volatile("cp.async.cg.shared.global [%0], [%1], 16;" :: "r"(s), "l"(g));
}
#define CP_COMMIT() asm volatile("cp.async.commit_group;" ::: "memory")
#define CP_WAIT1() asm volatile("cp.async.wait_group 1;" ::: "memory")
#define CP_WAIT0() asm volatile("cp.async.wait_group 0;" ::: "memory")

__device__ __forceinline__ float f2tf32f(float x) {
    uint32_t r;
    asm("cvt.rna.tf32.f32 %0, %1;" : "=r"(r) : "f"(x));
    return __uint_as_float(r);
}
__device__ __forceinline__ void mma_tf32(float* c, const uint32_t* a, const uint32_t* b) {
    asm volatile(
        "mma.sync.aligned.m16n8k8.row.col.f32.tf32.tf32.f32 "
        "{%0,%1,%2,%3}, {%4,%5,%6,%7}, {%8,%9}, {%0,%1,%2,%3};"
        : "+f"(c[0]), "+f"(c[1]), "+f"(c[2]), "+f"(c[3])
        : "r"(a[0]), "r"(a[1]), "r"(a[2]), "r"(a[3]), "r"(b[0]), "r"(b[1]));
}

// ---------------- pre-round HS -> g_HS (tf32) ------------------------------
__global__ __launch_bounds__(256) void preround_hs(const float* __restrict__ HS, int n4) {
    int i = blockIdx.x * blockDim.x + threadIdx.x;
    if (i >= n4) return;
    float4 v = ((const float4*)HS)[i];
    v.x = f2tf32f(v.x); v.y = f2tf32f(v.y); v.z = f2tf32f(v.z); v.w = f2tf32f(v.w);
    ((float4*)g_HS)[i] = v;
}

// ---------------- Fused: PA[b] = (HS[b] @ M) @ HS[b]^T / 128 ---------------
// CTA = 128 M-rows (2 boards). 8 n-chunks of 128:
//   MMA1: T_chunk(128x128) = HS(128x1024) @ M[:,chunk], k double-buffered
//   stage T_chunk (tf32) -> smem; MMA2: acc2 += T_chunk @ HSn^T (diag warps)
// smem floats: A 2x(128*36)=9216 | B 2x(128*36)=9216 | TS 128*132=16896 | HN 128*132=16896
#define F_A0 0
#define F_A1 4608
#define F_B0 9216
#define F_B1 13824
#define F_TS 18432
#define F_HN 35328
#define F_SMEM (52224 * 4)    // 208896 bytes

__global__ __launch_bounds__(256, 1) void fused_mma(float* __restrict__ PA) {
    extern __shared__ float smem[];
    uint32_t sb = smem_u32(smem);
    int tid = threadIdx.x, wid = tid >> 5, lane = tid & 31;
    int wm = wid >> 2, wn = wid & 3;          // 2 x 4 warp grid
    int lr = lane >> 2, lc = lane & 3;
    int m_base = blockIdx.x * 128;            // boards m_base/64, m_base/64+1
    const float* Ag = g_HS + (size_t)m_base * HIDDEN;
    bool useful = (wm == 0) ? (wn < 2) : (wn >= 2);

    float acc2[4][4][4];
#pragma unroll
    for (int i = 0; i < 4; i++)
#pragma unroll
        for (int j = 0; j < 4; j++)
#pragma unroll
            for (int t = 0; t < 4; t++) acc2[i][j][t] = 0.0f;

    for (int nch = 0; nch < 8; nch++) {
        int n0 = nch * 128;

        // issue HSn tile (128 x 128 floats) + first k-chunk as group 0
#pragma unroll
        for (int it = 0; it < 16; it++) {
            int idx = tid + it * 256;
            int row = idx >> 5, seg = idx & 31;
            cp_async16(sb + (F_HN + row * 132 + seg * 4) * 4,
                       Ag + (size_t)row * HIDDEN + n0 + seg * 4);
        }
        // k-chunk prefetch helper
        auto prefetchK = [&](int kc, int stg) {
            int k0 = kc * 32;
            uint32_t sA = sb + (stg ? F_A1 : F_A0) * 4;
            uint32_t sB = sb + (stg ? F_B1 : F_B0) * 4;
#pragma unroll
            for (int it = 0; it < 4; it++) {
                int idx = tid + it * 256;
                int row = idx >> 3, seg = idx & 7;
                cp_async16(sA + (row * 36 + seg * 4) * 4,
                           Ag + (size_t)row * HIDDEN + k0 + seg * 4);
            }
#pragma unroll
            for (int it = 0; it < 4; it++) {
                int idx = tid + it * 256;
                int row = idx >> 3, seg = idx & 7;
                cp_async16(sB + (row * 36 + seg * 4) * 4,
                           g_M + (size_t)(n0 + row) * HIDDEN + k0 + seg * 4);
            }
        };
        prefetchK(0, 0);
        CP_COMMIT();

        float acc1[4][4][4];
#pragma unroll
        for (int i = 0; i < 4; i++)
#pragma unroll
            for (int j = 0; j < 4; j++)
#pragma unroll
                for (int t = 0; t < 4; t++) acc1[i][j][t] = 0.0f;

        for (int kc = 0; kc < 32; kc++) {
            int stg = kc & 1;
            if (kc < 31) { prefetchK(kc + 1, stg ^ 1); CP_COMMIT(); CP_WAIT1(); }
            else         { CP_WAIT0(); }
            __syncthreads();
            const uint32_t* As = (const uint32_t*)(smem + (stg ? F_A1 : F_A0));
            const uint32_t* Bs = (const uint32_t*)(smem + (stg ? F_B1 : F_B0));
#pragma unroll
            for (int ks = 0; ks < 4; ks++) {
                int kk = ks * 8;
                uint32_t a[4][4], b[4][2];
#pragma unroll
                for (int mi = 0; mi < 4; mi++) {
                    int r = wm * 64 + mi * 16 + lr;
                    a[mi][0] = As[r * 36 + kk + lc];
                    a[mi][1] = As[(r + 8) * 36 + kk + lc];
                    a[mi][2] = As[r * 36 + kk + lc + 4];
                    a[mi][3] = As[(r + 8) * 36 + kk + lc + 4];
                }
#pragma unroll
                for (int ni = 0; ni < 4; ni++) {
                    int n = wn * 32 + ni * 8 + lr;
                    b[ni][0] = Bs[n * 36 + kk + lc];
                    b[ni][1] = Bs[n * 36 + kk + lc + 4];
                }
#pragma unroll
                for (int mi = 0; mi < 4; mi++)
#pragma unroll
                    for (int ni = 0; ni < 4; ni++)
                        mma_tf32(acc1[mi][ni], a[mi], b[ni]);
            }
            __syncthreads();
        }

        // stage T_chunk -> smem (tf32-rounded)
        float* TS = smem + F_TS;
#pragma unroll
        for (int mi = 0; mi < 4; mi++) {
            int r = wm * 64 + mi * 16 + lr;
#pragma unroll
            for (int ni = 0; ni < 4; ni++) {
                int col = wn * 32 + ni * 8 + lc * 2;
                *(float2*)&TS[r * 132 + col] =
                    make_float2(f2tf32f(acc1[mi][ni][0]), f2tf32f(acc1[mi][ni][1]));
                *(float2*)&TS[(r + 8) * 132 + col] =
                    make_float2(f2tf32f(acc1[mi][ni][2]), f2tf32f(acc1[mi][ni][3]));
            }
        }
        __syncthreads();

        // MMA2: acc2 += T_chunk @ HSn^T (board-diagonal warps only)
        if (useful) {
            const uint32_t* Ts = (const uint32_t*)(smem + F_TS);
            const uint32_t* Hn = (const uint32_t*)(smem + F_HN);
#pragma unroll
            for (int k2 = 0; k2 < 16; k2++) {
                int kk = k2 * 8;
                uint32_t a[4][4], b[4][2];
#pragma unroll
                for (int mi = 0; mi < 4; mi++) {
                    int r = wm * 64 + mi * 16 + lr;
                    a[mi][0] = Ts[r * 132 + kk + lc];
                    a[mi][1] = Ts[(r + 8) * 132 + kk + lc];
                    a[mi][2] = Ts[r * 132 + kk + lc + 4];
                    a[mi][3] = Ts[(r + 8) * 132 + kk + lc + 4];
                }
#pragma unroll
                for (int ni = 0; ni < 4; ni++) {
                    int j = wn * 32 + ni * 8 + lr;
                    b[ni][0] = Hn[j * 132 + kk + lc];
                    b[ni][1] = Hn[j * 132 + kk + lc + 4];
                }
#pragma unroll
                for (int mi = 0; mi < 4; mi++)
#pragma unroll
                    for (int ni = 0; ni < 4; ni++)
                        mma_tf32(acc2[mi][ni], a[mi], b[ni]);
            }
        }
        __syncthreads();   // protect TS/HN before next n-chunk overwrites
    }

    // epilogue: write PA board-diagonal blocks, scaled 1/128
    if (useful) {
        const float s = 1.0f / 128.0f;
        int board = (m_base >> 6) + wm;
        float* pa = PA + (size_t)board * 4096;
#pragma unroll
        for (int mi = 0; mi < 4; mi++) {
            int r = mi * 16 + lr;
#pragma unroll
            for (int ni = 0; ni < 4; ni++) {
                int col = (wn * 32 + ni * 8 + lc * 2) - wm * 64;
                *(float2*)&pa[r * 64 + col] =
                    make_float2(acc2[mi][ni][0] * s, acc2[mi][ni][1] * s);
                *(float2*)&pa[(r + 8) * 64 + col] =
                    make_float2(acc2[mi][ni][2] * s, acc2[mi][ni][3] * s);
            }
        }
    }
}

// ---------------- colmap: 16-segment parallel build + ordered merge --------
__global__ void build_colmap_seg(const float* __restrict__ pm) {
    int c = blockIdx.x * blockDim.x + threadIdx.x;
    int seg = blockIdx.y;
    if (c >= NCOLS) return;
    int r0 = seg * 268, r1 = r0 + 268;
    if (r1 > NROWS_PM) r1 = NROWS_PM;
    int n = 0;
    for (int r = r0; r < r1; r++) {
        if (pm[(size_t)r * NCOLS + c] != 0.0f) {
            if (n < 8) g_rowsS[(seg * NCOLS + c) * 8 + n] = r;
            n++;
        }
    }
    g_cntS[seg * NCOLS + c] = (n > 8) ? 8 : n;
}
__global__ void merge_colmap() {
    int c = blockIdx.x * blockDim.x + threadIdx.x;
    if (c >= NCOLS) return;
    int n = 0;
    for (int seg = 0; seg < NSEG; seg++) {
        int m = g_cntS[seg * NCOLS + c];
        for (int t = 0; t < m && n < 16; t++)
            g_rows[c * 16 + n++] = g_rowsS[(seg * NCOLS + c) * 8 + t];
    }
    g_cnt[c] = n;
}

// ---------------- g_M = Wk^T @ Wq (tf32-rounded) ---------------------------
__global__ __launch_bounds__(256) void gemm_tn_1024(
    const float* __restrict__ A, const float* __restrict__ B) {
    __shared__ float As[8][128];
    __shared__ float Bs[8][128];
    int bi = blockIdx.y, bj = blockIdx.x;
    int tid = threadIdx.x;
    int lrow = tid >> 5;
    int lcol = (tid & 31) * 4;
    int tx = tid & 15, ty = tid >> 4;
    const float* Ap = A + (size_t)lrow * HIDDEN + bi * 128 + lcol;
    const float* Bp = B + (size_t)lrow * HIDDEN + bj * 128 + lcol;
    float acc[8][8];
#pragma unroll
    for (int i = 0; i < 8; i++)
#pragma unroll
        for (int j = 0; j < 8; j++) acc[i][j] = 0.0f;
    for (int k0 = 0; k0 < HIDDEN; k0 += 8) {
        *(float4*)&As[lrow][lcol] = *(const float4*)(Ap + (size_t)k0 * HIDDEN);
        *(float4*)&Bs[lrow][lcol] = *(const float4*)(Bp + (size_t)k0 * HIDDEN);
        __syncthreads();
#pragma unroll
        for (int k = 0; k < 8; k++) {
            float a[8], b[8];
            *(float4*)&a[0] = *(float4*)&As[k][ty * 4];
            *(float4*)&a[4] = *(float4*)&As[k][64 + ty * 4];
            *(float4*)&b[0] = *(float4*)&Bs[k][tx * 4];
            *(float4*)&b[4] = *(float4*)&Bs[k][64 + tx * 4];
#pragma unroll
            for (int i = 0; i < 8; i++)
#pragma unroll
                for (int j = 0; j < 8; j++) acc[i][j] += a[i] * b[j];
        }
        __syncthreads();
    }
#pragma unroll
    for (int ih = 0; ih < 2; ih++)
#pragma unroll
        for (int i = 0; i < 4; i++) {
            int row = bi * 128 + ih * 64 + ty * 4 + i;
#pragma unroll
            for (int jh = 0; jh < 2; jh++) {
                float4 v = make_float4(f2tf32f(acc[ih * 4 + i][jh * 4 + 0]),
                                       f2tf32f(acc[ih * 4 + i][jh * 4 + 1]),
                                       f2tf32f(acc[ih * 4 + i][jh * 4 + 2]),
                                       f2tf32f(acc[ih * 4 + i][jh * 4 + 3]));
                *(float4*)&g_M[(size_t)row * HIDDEN + bj * 128 + jh * 64 + tx * 4] = v;
            }
        }
}

// ---------------- Weff: zero + 48-block partial accumulate -----------------
__global__ void weff_zero() {
    int i = blockIdx.x * blockDim.x + threadIdx.x;
    if (i < 3 * HIDDEN) g_Weff[i] = 0.0f;
}
__global__ void weff_partial(const float* __restrict__ Wpo, const float* __restrict__ Wpk) {
    int i = blockIdx.x;
    int seg = blockIdx.y;
    int tid = threadIdx.x;
    int c0 = seg * 64;
    float acc[4] = {0.f, 0.f, 0.f, 0.f};
    for (int c = c0; c < c0 + 64; c++) {
        float w = Wpo[i * HIDDEN + c];
        const float* row = Wpk + (size_t)c * HIDDEN;
#pragma unroll
        for (int j = 0; j < 4; j++) acc[j] += w * row[j * 256 + tid];
    }
#pragma unroll
    for (int j = 0; j < 4; j++) atomicAdd(&g_Weff[i * HIDDEN + j * 256 + tid], acc[j]);
}

// ---------------- promo offsets (full-precision HS) ------------------------
__global__ void promo_kernel(const float* __restrict__ HS) {
    int b = blockIdx.x;
    int tid = threadIdx.x;
    int lane = tid & 31, w = tid >> 5;
    for (int p = w; p < 24; p += 8) {
        int i = p >> 3;
        int s = p & 7;
        const float* h = HS + ((size_t)b * 64 + 48 + s) * HIDDEN;
        const float* we = g_Weff + i * HIDDEN;
        float acc = 0.f;
        for (int d = lane; d < HIDDEN; d += 32) acc += h[d] * we[d];
#pragma unroll
        for (int o = 16; o; o >>= 1) acc += __shfl_xor_sync(0xFFFFFFFFu, acc, o);
        if (lane == 0) g_PO[b * 24 + i * 8 + s] = acc;
    }
}

// ---------------- final sparse gather --------------------------------------
__global__ void gather_kernel(float* __restrict__ PL, const float* __restrict__ PAfull) {
    int c = blockIdx.x * blockDim.x + threadIdx.x;
    int b = blockIdx.y;
    if (c >= NCOLS) return;
    const float* pa = PAfull + (size_t)b * 4096;
    int n = g_cnt[c];
    float v = 0.f;
    for (int t = 0; t < n; t++) {
        int r = g_rows[c * 16 + t];
        if (r < 4096) {
            v += pa[r] * 0.125f;
        } else {
            int u = r - 4096;
            int r8 = u / 24, rem = u % 24;
            int cc = rem / 3, ii = rem % 3;
            v += pa[(48 + r8) * 64 + 56 + cc] + 8.0f * g_PO[b * 24 + ii * 8 + cc];
        }
    }
    PL[(size_t)b * NCOLS + c] = v;
}

// ---------------- launcher -------------------------------------------------
extern "C" void kernel_launch(void* const* d_in, const int* in_sizes, int n_in,
                              void* d_out, int out_size) {
    const float* HS  = (const float*)d_in[0];
    const float* Wq  = (const float*)d_in[1];
    const float* Wk  = (const float*)d_in[2];
    const float* Wpk = (const float*)d_in[3];
    const float* Wpo = (const float*)d_in[4];
    const float* pm  = (const float*)d_in[5];
    int B = in_sizes[0] / (64 * HIDDEN);

    float* out = (float*)d_out;
    float* PL = out;
    float* PA = out + (size_t)B * NCOLS;

    cudaFuncSetAttribute(fused_mma, cudaFuncAttributeMaxDynamicSharedMemorySize, F_SMEM);

    int n4 = (B * 64 * HIDDEN) / 4;
    preround_hs<<<(n4 + 255) / 256, 256>>>(HS, n4);
    build_colmap_seg<<<dim3((NCOLS + 255) / 256, NSEG), 256>>>(pm);
    merge_colmap<<<(NCOLS + 255) / 256, 256>>>();
    gemm_tn_1024<<<dim3(8, 8), 256>>>(Wk, Wq);
    weff_zero<<<12, 256>>>();
    weff_partial<<<dim3(3, 16), 256>>>(Wpo, Wpk);
    fused_mma<<<(B * 64) / 128, 256, F_SMEM>>>(PA);
    promo_kernel<<<B, 256>>>(HS);
    gather_kernel<<<dim3((NCOLS + 255) / 256, B), 256>>>(PL, PA);
}

// round 9
// speedup vs baseline: 1.7090x; 1.7090x over previous
#include <cuda_runtime.h>
#include <cuda_fp16.h>
#include <cstdint>

#define HIDDEN 1024
#define NCOLS 1858
#define NROWS_PM 4288
#define MAXB 2048
#define NSEG 16

// ---------------- scratch (device globals: allocation-free) ----------------
__device__ __half g_HSh[(size_t)MAXB * 64 * HIDDEN]; // HS in fp16
__device__ __half g_Th[(size_t)MAXB * 64 * HIDDEN];  // T = HS @ M in fp16
__device__ __half g_Mh[HIDDEN * HIDDEN];             // M^T in fp16 (n rows, k contiguous)
__device__ float  g_Mp[4][HIDDEN * HIDDEN];          // split-K partials
__device__ float  g_Weff[3 * HIDDEN];
__device__ float  g_PO[MAXB * 24];
__device__ int    g_cnt[NCOLS];
__device__ int    g_rows[NCOLS * 16];
__device__ int    g_cntS[NSEG * NCOLS];
__device__ int    g_rowsS[NSEG * NCOLS * 8];

// ---------------- PTX helpers (arch-agnostic: sm_80+ only) -----------------
__device__ __forceinline__ uint32_t smem_u32(const void* p) {
    uint32_t a;
    asm("{ .reg .u64 t; cvta.to.shared.u64 t, %1; cvt.u32.u64 %0, t; }" : "=r"(a) : "l"(p));
    return a;
}
__device__ __forceinline__ void cp_async16(uint32_t s, const void* g) {
    asm volatile("cp.async.cg.shared.global [%0], [%1], 16;" :: "r"(s), "l"(g));
}
#define CP_COMMIT() asm volatile("cp.async.commit_group;" ::: "memory")
#define CP_WAIT1() asm volatile("cp.async.wait_group 1;" ::: "memory")
#define CP_WAIT0() asm volatile("cp.async.wait_group 0;" ::: "memory")

__device__ __forceinline__ void mma_f16(float* c, const uint32_t* a, const uint32_t* b) {
    asm volatile(
        "mma.sync.aligned.m16n8k16.row.col.f32.f16.f16.f32 "
        "{%0,%1,%2,%3}, {%4,%5,%6,%7}, {%8,%9}, {%0,%1,%2,%3};"
        : "+f"(c[0]), "+f"(c[1]), "+f"(c[2]), "+f"(c[3])
        : "r"(a[0]), "r"(a[1]), "r"(a[2]), "r"(a[3]), "r"(b[0]), "r"(b[1]));
}
__device__ __forceinline__ uint32_t pack_h2(float x, float y) {
    __half2 h = __floats2half2_rn(x, y);
    return *(uint32_t*)&h;
}

// ---------------- preround: HS fp32 -> g_HSh fp16 --------------------------
__global__ __launch_bounds__(256) void preround_hs(const float* __restrict__ HS, int n4) {
    int i = blockIdx.x * blockDim.x + threadIdx.x;
    if (i >= n4) return;
    float4 v = ((const float4*)HS)[i];
    uint2 w;
    w.x = pack_h2(v.x, v.y);
    w.y = pack_h2(v.z, v.w);
    ((uint2*)g_HSh)[i] = w;
}

// ---------------- Pass1: T = HS @ M via fp16 mma.sync ----------------------
// CTA tile 128(M) x 256(N), k-chunk 32, 8 warps (2x4), warp tile 64x64.
// smem rows stride 40 halves (conflict-free for half2 fragment loads).
#define P1_AH 0
#define P1_BH (128 * 40)
#define P1_STG (128 * 40 + 256 * 40)            // 15360 halves/stage
#define P1_SMEMB (2 * P1_STG * 2)               // 61440 bytes

__global__ __launch_bounds__(256, 1) void pass1_mma() {
    extern __shared__ __half hsm[];
    uint32_t sb = smem_u32(hsm);
    int tid = threadIdx.x, wid = tid >> 5, lane = tid & 31;
    int wm = wid >> 2, wn = wid & 3;
    int lr = lane >> 2, lc = lane & 3;
    int m_base = blockIdx.y * 128;
    int n_base = blockIdx.x * 256;
    const __half* Ag = g_HSh + (size_t)m_base * HIDDEN;

    auto prefetch = [&](int chunk, int stg) {
        int k0 = chunk * 32;
        uint32_t sA = sb + (stg * P1_STG + P1_AH) * 2;
        uint32_t sB = sb + (stg * P1_STG + P1_BH) * 2;
#pragma unroll
        for (int it = 0; it < 2; it++) {                 // A: 512 x 16B
            int idx = tid + it * 256;
            int row = idx >> 2, seg = idx & 3;
            cp_async16(sA + (row * 40 + seg * 8) * 2,
                       Ag + (size_t)row * HIDDEN + k0 + seg * 8);
        }
#pragma unroll
        for (int it = 0; it < 4; it++) {                 // B: 1024 x 16B
            int idx = tid + it * 256;
            int row = idx >> 2, seg = idx & 3;
            cp_async16(sB + (row * 40 + seg * 8) * 2,
                       g_Mh + (size_t)(n_base + row) * HIDDEN + k0 + seg * 8);
        }
    };

    float acc[4][8][4];
#pragma unroll
    for (int i = 0; i < 4; i++)
#pragma unroll
        for (int j = 0; j < 8; j++)
#pragma unroll
            for (int t = 0; t < 4; t++) acc[i][j][t] = 0.0f;

    prefetch(0, 0);
    CP_COMMIT();

    for (int c = 0; c < 32; c++) {
        int stg = c & 1;
        if (c < 31) { prefetch(c + 1, stg ^ 1); CP_COMMIT(); CP_WAIT1(); }
        else        { CP_WAIT0(); }
        __syncthreads();
        const uint32_t* Au = (const uint32_t*)(hsm + stg * P1_STG + P1_AH);
        const uint32_t* Bu = (const uint32_t*)(hsm + stg * P1_STG + P1_BH);
#pragma unroll
        for (int ks = 0; ks < 2; ks++) {         // two k16 steps per chunk
            int k8 = ks * 8;                     // uint32 offset within row
            uint32_t a[4][4], b[8][2];
#pragma unroll
            for (int mi = 0; mi < 4; mi++) {
                int r = wm * 64 + mi * 16 + lr;
                a[mi][0] = Au[r * 20 + k8 + lc];
                a[mi][1] = Au[(r + 8) * 20 + k8 + lc];
                a[mi][2] = Au[r * 20 + k8 + 4 + lc];
                a[mi][3] = Au[(r + 8) * 20 + k8 + 4 + lc];
            }
#pragma unroll
            for (int ni = 0; ni < 8; ni++) {
                int n = wn * 64 + ni * 8 + lr;
                b[ni][0] = Bu[n * 20 + k8 + lc];
                b[ni][1] = Bu[n * 20 + k8 + 4 + lc];
            }
#pragma unroll
            for (int mi = 0; mi < 4; mi++)
#pragma unroll
                for (int ni = 0; ni < 8; ni++)
                    mma_f16(acc[mi][ni], a[mi], b[ni]);
        }
        __syncthreads();
    }

    // epilogue: store T as fp16
#pragma unroll
    for (int mi = 0; mi < 4; mi++) {
        int r0 = m_base + wm * 64 + mi * 16 + lr;
#pragma unroll
        for (int ni = 0; ni < 8; ni++) {
            int col = n_base + wn * 64 + ni * 8 + lc * 2;
            *(uint32_t*)&g_Th[(size_t)r0 * HIDDEN + col] = pack_h2(acc[mi][ni][0], acc[mi][ni][1]);
            *(uint32_t*)&g_Th[(size_t)(r0 + 8) * HIDDEN + col] = pack_h2(acc[mi][ni][2], acc[mi][ni][3]);
        }
    }
}

// ---------------- Pass2: PA[b] = T[b] @ HS[b]^T / 128 (fp16 mma) -----------
__global__ __launch_bounds__(128) void pass2_mma(float* __restrict__ PA) {
    __shared__ __half Ts[2][64 * 40];
    __shared__ __half Hs[2][64 * 40];
    int b = blockIdx.x;
    int tid = threadIdx.x, wid = tid >> 5, lane = tid & 31;
    int wm = wid >> 1, wn = wid & 1;
    int lr = lane >> 2, lc = lane & 3;

    const __half* Tg = g_Th + (size_t)b * 64 * HIDDEN;
    const __half* Hg = g_HSh + (size_t)b * 64 * HIDDEN;
    uint32_t sT0 = smem_u32(&Ts[0][0]);
    uint32_t sH0 = smem_u32(&Hs[0][0]);

    auto prefetch = [&](int chunk, int stg) {
        int k0 = chunk * 32;
        uint32_t sT = sT0 + stg * 64 * 40 * 2;
        uint32_t sH = sH0 + stg * 64 * 40 * 2;
#pragma unroll
        for (int it = 0; it < 2; it++) {
            int idx = tid + it * 128;
            int row = idx >> 2, seg = idx & 3;
            cp_async16(sT + (row * 40 + seg * 8) * 2, Tg + (size_t)row * HIDDEN + k0 + seg * 8);
            cp_async16(sH + (row * 40 + seg * 8) * 2, Hg + (size_t)row * HIDDEN + k0 + seg * 8);
        }
    };

    float acc[2][4][4];
#pragma unroll
    for (int i = 0; i < 2; i++)
#pragma unroll
        for (int j = 0; j < 4; j++)
#pragma unroll
            for (int t = 0; t < 4; t++) acc[i][j][t] = 0.0f;

    prefetch(0, 0);
    CP_COMMIT();

    for (int c = 0; c < 32; c++) {
        int stg = c & 1;
        if (c < 31) { prefetch(c + 1, stg ^ 1); CP_COMMIT(); CP_WAIT1(); }
        else        { CP_WAIT0(); }
        __syncthreads();
        const uint32_t* Au = (const uint32_t*)Ts[stg];
        const uint32_t* Bu = (const uint32_t*)Hs[stg];
#pragma unroll
        for (int ks = 0; ks < 2; ks++) {
            int k8 = ks * 8;
            uint32_t a[2][4], bb[4][2];
#pragma unroll
            for (int mi = 0; mi < 2; mi++) {
                int r = wm * 32 + mi * 16 + lr;
                a[mi][0] = Au[r * 20 + k8 + lc];
                a[mi][1] = Au[(r + 8) * 20 + k8 + lc];
                a[mi][2] = Au[r * 20 + k8 + 4 + lc];
                a[mi][3] = Au[(r + 8) * 20 + k8 + 4 + lc];
            }
#pragma unroll
            for (int ni = 0; ni < 4; ni++) {
                int n = wn * 32 + ni * 8 + lr;
                bb[ni][0] = Bu[n * 20 + k8 + lc];
                bb[ni][1] = Bu[n * 20 + k8 + 4 + lc];
            }
#pragma unroll
            for (int mi = 0; mi < 2; mi++)
#pragma unroll
                for (int ni = 0; ni < 4; ni++)
                    mma_f16(acc[mi][ni], a[mi], bb[ni]);
        }
        __syncthreads();
    }

    const float s = 1.0f / 128.0f;
    float* pa = PA + (size_t)b * 4096;
#pragma unroll
    for (int mi = 0; mi < 2; mi++) {
        int r0 = wm * 32 + mi * 16 + lr;
#pragma unroll
        for (int ni = 0; ni < 4; ni++) {
            int col = wn * 32 + ni * 8 + lc * 2;
            *(float2*)&pa[r0 * 64 + col] = make_float2(acc[mi][ni][0] * s, acc[mi][ni][1] * s);
            *(float2*)&pa[(r0 + 8) * 64 + col] = make_float2(acc[mi][ni][2] * s, acc[mi][ni][3] * s);
        }
    }
}

// ---------------- colmap: 16-segment parallel build + ordered merge --------
__global__ void build_colmap_seg(const float* __restrict__ pm) {
    int c = blockIdx.x * blockDim.x + threadIdx.x;
    int seg = blockIdx.y;
    if (c >= NCOLS) return;
    int r0 = seg * 268, r1 = r0 + 268;
    if (r1 > NROWS_PM) r1 = NROWS_PM;
    int n = 0;
    for (int r = r0; r < r1; r++) {
        if (pm[(size_t)r * NCOLS + c] != 0.0f) {
            if (n < 8) g_rowsS[(seg * NCOLS + c) * 8 + n] = r;
            n++;
        }
    }
    g_cntS[seg * NCOLS + c] = (n > 8) ? 8 : n;
}
__global__ void merge_colmap() {
    int c = blockIdx.x * blockDim.x + threadIdx.x;
    if (c >= NCOLS) return;
    int n = 0;
    for (int seg = 0; seg < NSEG; seg++) {
        int m = g_cntS[seg * NCOLS + c];
        for (int t = 0; t < m && n < 16; t++)
            g_rows[c * 16 + n++] = g_rowsS[(seg * NCOLS + c) * 8 + t];
    }
    g_cnt[c] = n;
}

// ---------------- g_M partials: split-K x4, deterministic ------------------
// partial[ks][i,j] = sum_{k in seg} Wk[k,i]*Wq[k,j]   (i.e. (Wk^T Wq) seg)
__global__ __launch_bounds__(256) void gemm_tn_part(
    const float* __restrict__ A, const float* __restrict__ B) {
    __shared__ float As[8][128];
    __shared__ float Bs[8][128];
    int bi = blockIdx.y, bj = blockIdx.x, ks = blockIdx.z;
    int tid = threadIdx.x;
    int lrow = tid >> 5;
    int lcol = (tid & 31) * 4;
    int tx = tid & 15, ty = tid >> 4;
    int kbase = ks * 256;
    const float* Ap = A + (size_t)(kbase + lrow) * HIDDEN + bi * 128 + lcol;
    const float* Bp = B + (size_t)(kbase + lrow) * HIDDEN + bj * 128 + lcol;
    float acc[8][8];
#pragma unroll
    for (int i = 0; i < 8; i++)
#pragma unroll
        for (int j = 0; j < 8; j++) acc[i][j] = 0.0f;
    for (int k0 = 0; k0 < 256; k0 += 8) {
        *(float4*)&As[lrow][lcol] = *(const float4*)(Ap + (size_t)k0 * HIDDEN);
        *(float4*)&Bs[lrow][lcol] = *(const float4*)(Bp + (size_t)k0 * HIDDEN);
        __syncthreads();
#pragma unroll
        for (int k = 0; k < 8; k++) {
            float a[8], b[8];
            *(float4*)&a[0] = *(float4*)&As[k][ty * 4];
            *(float4*)&a[4] = *(float4*)&As[k][64 + ty * 4];
            *(float4*)&b[0] = *(float4*)&Bs[k][tx * 4];
            *(float4*)&b[4] = *(float4*)&Bs[k][64 + tx * 4];
#pragma unroll
            for (int i = 0; i < 8; i++)
#pragma unroll
                for (int j = 0; j < 8; j++) acc[i][j] += a[i] * b[j];
        }
        __syncthreads();
    }
    float* Mout = g_Mp[ks];
#pragma unroll
    for (int ih = 0; ih < 2; ih++)
#pragma unroll
        for (int i = 0; i < 4; i++) {
            int row = bi * 128 + ih * 64 + ty * 4 + i;
#pragma unroll
            for (int jh = 0; jh < 2; jh++) {
                float4 v = make_float4(acc[ih * 4 + i][jh * 4 + 0], acc[ih * 4 + i][jh * 4 + 1],
                                       acc[ih * 4 + i][jh * 4 + 2], acc[ih * 4 + i][jh * 4 + 3]);
                *(float4*)&Mout[(size_t)row * HIDDEN + bj * 128 + jh * 64 + tx * 4] = v;
            }
        }
}
__global__ __launch_bounds__(256) void mh_combine() {
    int i = blockIdx.x * blockDim.x + threadIdx.x;
    if (i >= HIDDEN * HIDDEN) return;
    float s = g_Mp[0][i] + g_Mp[1][i] + g_Mp[2][i] + g_Mp[3][i];
    g_Mh[i] = __float2half_rn(s);
}

// ---------------- Weff: zero + 48-block partial accumulate -----------------
__global__ void weff_zero() {
    int i = blockIdx.x * blockDim.x + threadIdx.x;
    if (i < 3 * HIDDEN) g_Weff[i] = 0.0f;
}
__global__ void weff_partial(const float* __restrict__ Wpo, const float* __restrict__ Wpk) {
    int i = blockIdx.x;
    int seg = blockIdx.y;
    int tid = threadIdx.x;
    int c0 = seg * 64;
    float acc[4] = {0.f, 0.f, 0.f, 0.f};
    for (int c = c0; c < c0 + 64; c++) {
        float w = Wpo[i * HIDDEN + c];
        const float* row = Wpk + (size_t)c * HIDDEN;
#pragma unroll
        for (int j = 0; j < 4; j++) acc[j] += w * row[j * 256 + tid];
    }
#pragma unroll
    for (int j = 0; j < 4; j++) atomicAdd(&g_Weff[i * HIDDEN + j * 256 + tid], acc[j]);
}

// ---------------- promo offsets (full-precision HS) ------------------------
__global__ void promo_kernel(const float* __restrict__ HS) {
    int b = blockIdx.x;
    int tid = threadIdx.x;
    int lane = tid & 31, w = tid >> 5;
    for (int p = w; p < 24; p += 8) {
        int i = p >> 3;
        int s = p & 7;
        const float* h = HS + ((size_t)b * 64 + 48 + s) * HIDDEN;
        const float* we = g_Weff + i * HIDDEN;
        float acc = 0.f;
        for (int d = lane; d < HIDDEN; d += 32) acc += h[d] * we[d];
#pragma unroll
        for (int o = 16; o; o >>= 1) acc += __shfl_xor_sync(0xFFFFFFFFu, acc, o);
        if (lane == 0) g_PO[b * 24 + i * 8 + s] = acc;
    }
}

// ---------------- final sparse gather --------------------------------------
__global__ void gather_kernel(float* __restrict__ PL, const float* __restrict__ PAfull) {
    int c = blockIdx.x * blockDim.x + threadIdx.x;
    int b = blockIdx.y;
    if (c >= NCOLS) return;
    const float* pa = PAfull + (size_t)b * 4096;
    int n = g_cnt[c];
    float v = 0.f;
    for (int t = 0; t < n; t++) {
        int r = g_rows[c * 16 + t];
        if (r < 4096) {
            v += pa[r] * 0.125f;
        } else {
            int u = r - 4096;
            int r8 = u / 24, rem = u % 24;
            int cc = rem / 3, ii = rem % 3;
            v += pa[(48 + r8) * 64 + 56 + cc] + 8.0f * g_PO[b * 24 + ii * 8 + cc];
        }
    }
    PL[(size_t)b * NCOLS + c] = v;
}

// ---------------- launcher -------------------------------------------------
extern "C" void kernel_launch(void* const* d_in, const int* in_sizes, int n_in,
                              void* d_out, int out_size) {
    const float* HS  = (const float*)d_in[0];
    const float* Wq  = (const float*)d_in[1];
    const float* Wk  = (const float*)d_in[2];
    const float* Wpk = (const float*)d_in[3];
    const float* Wpo = (const float*)d_in[4];
    const float* pm  = (const float*)d_in[5];
    int B = in_sizes[0] / (64 * HIDDEN);

    float* out = (float*)d_out;
    float* PL = out;
    float* PA = out + (size_t)B * NCOLS;

    cudaFuncSetAttribute(pass1_mma, cudaFuncAttributeMaxDynamicSharedMemorySize, P1_SMEMB);

    int n4 = (B * 64 * HIDDEN) / 4;
    preround_hs<<<(n4 + 255) / 256, 256>>>(HS, n4);
    build_colmap_seg<<<dim3((NCOLS + 255) / 256, NSEG), 256>>>(pm);
    merge_colmap<<<(NCOLS + 255) / 256, 256>>>();
    gemm_tn_part<<<dim3(8, 8, 4), 256>>>(Wk, Wq);          // partials of Wk^T Wq
    mh_combine<<<(HIDDEN * HIDDEN + 255) / 256, 256>>>();  // sum + fp16 round
    weff_zero<<<12, 256>>>();
    weff_partial<<<dim3(3, 16), 256>>>(Wpo, Wpk);
    pass1_mma<<<dim3(4, (B * 64) / 128), 256, P1_SMEMB>>>();
    pass2_mma<<<B, 128>>>(PA);
    promo_kernel<<<B, 256>>>(HS);
    gather_kernel<<<dim3((NCOLS + 255) / 256, B), 256>>>(PL, PA);
}

// round 11
// speedup vs baseline: 1.9509x; 1.1415x over previous
#include <cuda_runtime.h>
#include <cuda_fp16.h>
#include <cstdint>

#define HIDDEN 1024
#define NCOLS 1858
#define NROWS_PM 4288
#define MAXB 2048
#define NSEG 16

// ---------------- scratch (device globals: allocation-free) ----------------
__device__ __half g_HSh[(size_t)MAXB * 64 * HIDDEN]; // HS in fp16
__device__ __half g_Th[(size_t)MAXB * 64 * HIDDEN];  // T = HS @ M in fp16
__device__ __half g_Mh[HIDDEN * HIDDEN];             // M^T in fp16 (n rows, k contiguous)
__device__ float  g_Mp[4][HIDDEN * HIDDEN];          // split-K partials
__device__ float  g_Weff[3 * HIDDEN];
__device__ float  g_PO[MAXB * 24];
__device__ int    g_cnt[NCOLS];
__device__ int    g_rows[NCOLS * 16];
__device__ int    g_cntS[NSEG * NCOLS];
__device__ int    g_rowsS[NSEG * NCOLS * 8];

// ---------------- PTX helpers (arch-agnostic: sm_80+ only) -----------------
__device__ __forceinline__ uint32_t smem_u32(const void* p) {
    uint32_t a;
    asm("{ .reg .u64 t; cvta.to.shared.u64 t, %1; cvt.u32.u64 %0, t; }" : "=r"(a) : "l"(p));
    return a;
}
__device__ __forceinline__ void cp_async16(uint32_t s, const void* g) {
    asm volatile("cp.async.cg.shared.global [%0], [%1], 16;" :: "r"(s), "l"(g));
}
#define CP_COMMIT() asm volatile("cp.async.commit_group;" ::: "memory")
#define CP_WAIT1() asm volatile("cp.async.wait_group 1;" ::: "memory")
#define CP_WAIT0() asm volatile("cp.async.wait_group 0;" ::: "memory")

__device__ __forceinline__ void mma_f16(float* c, const uint32_t* a, const uint32_t* b) {
    asm volatile(
        "mma.sync.aligned.m16n8k16.row.col.f32.f16.f16.f32 "
        "{%0,%1,%2,%3}, {%4,%5,%6,%7}, {%8,%9}, {%0,%1,%2,%3};"
        : "+f"(c[0]), "+f"(c[1]), "+f"(c[2]), "+f"(c[3])
        : "r"(a[0]), "r"(a[1]), "r"(a[2]), "r"(a[3]), "r"(b[0]), "r"(b[1]));
}
__device__ __forceinline__ void ldm_x4(uint32_t* r, uint32_t addr) {
    asm volatile("ldmatrix.sync.aligned.m8n8.x4.shared.b16 {%0,%1,%2,%3}, [%4];"
        : "=r"(r[0]), "=r"(r[1]), "=r"(r[2]), "=r"(r[3]) : "r"(addr));
}
__device__ __forceinline__ uint32_t pack_h2(float x, float y) {
    __half2 h = __floats2half2_rn(x, y);
    return *(uint32_t*)&h;
}
// swizzled byte offset within a [rows x 32half] tile: row stride 64B,
// 16B-unit u in 0..3 stored at u ^ ((row>>1)&3)  (conflict-free for
// cp.async 16B writes and 8-row ldmatrix phases)
__device__ __forceinline__ uint32_t swz(int row, int ku) {
    return (uint32_t)(row * 64 + ((ku ^ ((row >> 1) & 3)) << 4));
}

// ---------------- preround: HS fp32 -> g_HSh fp16 --------------------------
__global__ __launch_bounds__(256) void preround_hs(const float* __restrict__ HS, int n4) {
    int i = blockIdx.x * blockDim.x + threadIdx.x;
    if (i >= n4) return;
    float4 v = ((const float4*)HS)[i];
    uint2 w;
    w.x = pack_h2(v.x, v.y);
    w.y = pack_h2(v.z, v.w);
    ((uint2*)g_HSh)[i] = w;
}

// ---------------- Pass1: T = HS @ M via fp16 mma + ldmatrix ----------------
// CTA tile 128(M) x 256(N), k-chunk 32, 8 warps (2x4), warp tile 64x64.
// smem: A 128x32h (8KB) + B 256x32h (16KB) per stage, swizzled 64B rows.
#define P1_STAGEB 24576
#define P1_SMEMB (2 * P1_STAGEB)      // 49152 bytes

__global__ __launch_bounds__(256, 1) void pass1_mma() {
    extern __shared__ __half hsm[];
    uint32_t sb = smem_u32(hsm);
    int tid = threadIdx.x, wid = tid >> 5, lane = tid & 31;
    int wm = wid >> 2, wn = wid & 3;
    int lr = lane >> 2, lc = lane & 3;
    int g = lane >> 3, tr = lane & 7;          // ldmatrix address groups
    int m_base = blockIdx.y * 128;
    int n_base = blockIdx.x * 256;
    const __half* Ag = g_HSh + (size_t)m_base * HIDDEN;

    auto prefetch = [&](int chunk, int stg) {
        int k0 = chunk * 32;
        uint32_t base = sb + stg * P1_STAGEB;
#pragma unroll
        for (int it = 0; it < 2; it++) {                 // A: 512 x 16B
            int idx = tid + it * 256;
            int r = idx >> 2, seg = idx & 3;
            cp_async16(base + swz(r, seg), Ag + (size_t)r * HIDDEN + k0 + seg * 8);
        }
#pragma unroll
        for (int it = 0; it < 4; it++) {                 // B: 1024 x 16B
            int idx = tid + it * 256;
            int r = idx >> 2, seg = idx & 3;
            cp_async16(base + 8192 + swz(r, seg),
                       g_Mh + (size_t)(n_base + r) * HIDDEN + k0 + seg * 8);
        }
    };

    float acc[4][8][4];
#pragma unroll
    for (int i = 0; i < 4; i++)
#pragma unroll
        for (int j = 0; j < 8; j++)
#pragma unroll
            for (int t = 0; t < 4; t++) acc[i][j][t] = 0.0f;

    prefetch(0, 0);
    CP_COMMIT();

    for (int c = 0; c < 32; c++) {
        int stg = c & 1;
        if (c < 31) { prefetch(c + 1, stg ^ 1); CP_COMMIT(); CP_WAIT1(); }
        else        { CP_WAIT0(); }
        __syncthreads();
        uint32_t sA = sb + stg * P1_STAGEB;
        uint32_t sB = sA + 8192;
#pragma unroll
        for (int ks = 0; ks < 2; ks++) {
            uint32_t a[4][4], b[8][2];
#pragma unroll
            for (int mi = 0; mi < 4; mi++) {
                int rr = wm * 64 + mi * 16 + ((g & 1) << 3) + tr;
                int ku = ks * 2 + (g >> 1);
                ldm_x4(a[mi], sA + swz(rr, ku));
            }
#pragma unroll
            for (int jj = 0; jj < 8; jj += 2) {
                int rr = wn * 64 + (jj + (g >> 1)) * 8 + tr;
                int ku = ks * 2 + (g & 1);
                uint32_t r4[4];
                ldm_x4(r4, sB + swz(rr, ku));
                b[jj][0] = r4[0]; b[jj][1] = r4[1];
                b[jj + 1][0] = r4[2]; b[jj + 1][1] = r4[3];
            }
#pragma unroll
            for (int mi = 0; mi < 4; mi++)
#pragma unroll
                for (int ni = 0; ni < 8; ni++)
                    mma_f16(acc[mi][ni], a[mi], b[ni]);
        }
        __syncthreads();
    }

    // epilogue: store T as fp16
#pragma unroll
    for (int mi = 0; mi < 4; mi++) {
        int r0 = m_base + wm * 64 + mi * 16 + lr;
#pragma unroll
        for (int ni = 0; ni < 8; ni++) {
            int col = n_base + wn * 64 + ni * 8 + lc * 2;
            *(uint32_t*)&g_Th[(size_t)r0 * HIDDEN + col] = pack_h2(acc[mi][ni][0], acc[mi][ni][1]);
            *(uint32_t*)&g_Th[(size_t)(r0 + 8) * HIDDEN + col] = pack_h2(acc[mi][ni][2], acc[mi][ni][3]);
        }
    }
}

// ---------------- Pass2: PA[b] = T[b] @ HS[b]^T / 128 (fp16 + ldmatrix) ----
__global__ __launch_bounds__(128) void pass2_mma(float* __restrict__ PA) {
    __shared__ __half Ts[2][64 * 32];
    __shared__ __half Hs[2][64 * 32];
    int b = blockIdx.x;
    int tid = threadIdx.x, wid = tid >> 5, lane = tid & 31;
    int wm = wid >> 1, wn = wid & 1;
    int lr = lane >> 2, lc = lane & 3;
    int g = lane >> 3, tr = lane & 7;

    const __half* Tg = g_Th + (size_t)b * 64 * HIDDEN;
    const __half* Hg = g_HSh + (size_t)b * 64 * HIDDEN;
    uint32_t sT0 = smem_u32(&Ts[0][0]);
    uint32_t sH0 = smem_u32(&Hs[0][0]);

    auto prefetch = [&](int chunk, int stg) {
        int k0 = chunk * 32;
        uint32_t sT = sT0 + stg * 4096;
        uint32_t sH = sH0 + stg * 4096;
#pragma unroll
        for (int it = 0; it < 2; it++) {                 // 256 x 16B each
            int idx = tid + it * 128;
            int r = idx >> 2, seg = idx & 3;
            cp_async16(sT + swz(r, seg), Tg + (size_t)r * HIDDEN + k0 + seg * 8);
            cp_async16(sH + swz(r, seg), Hg + (size_t)r * HIDDEN + k0 + seg * 8);
        }
    };

    float acc[2][4][4];
#pragma unroll
    for (int i = 0; i < 2; i++)
#pragma unroll
        for (int j = 0; j < 4; j++)
#pragma unroll
            for (int t = 0; t < 4; t++) acc[i][j][t] = 0.0f;

    prefetch(0, 0);
    CP_COMMIT();

    for (int c = 0; c < 32; c++) {
        int stg = c & 1;
        if (c < 31) { prefetch(c + 1, stg ^ 1); CP_COMMIT(); CP_WAIT1(); }
        else        { CP_WAIT0(); }
        __syncthreads();
        uint32_t sT = sT0 + stg * 4096;
        uint32_t sH = sH0 + stg * 4096;
#pragma unroll
        for (int ks = 0; ks < 2; ks++) {
            uint32_t a[2][4], bb[4][2];
#pragma unroll
            for (int mi = 0; mi < 2; mi++) {
                int rr = wm * 32 + mi * 16 + ((g & 1) << 3) + tr;
                int ku = ks * 2 + (g >> 1);
                ldm_x4(a[mi], sT + swz(rr, ku));
            }
#pragma unroll
            for (int jj = 0; jj < 4; jj += 2) {
                int rr = wn * 32 + (jj + (g >> 1)) * 8 + tr;
                int ku = ks * 2 + (g & 1);
                uint32_t r4[4];
                ldm_x4(r4, sH + swz(rr, ku));
                bb[jj][0] = r4[0]; bb[jj][1] = r4[1];
                bb[jj + 1][0] = r4[2]; bb[jj + 1][1] = r4[3];
            }
#pragma unroll
            for (int mi = 0; mi < 2; mi++)
#pragma unroll
                for (int ni = 0; ni < 4; ni++)
                    mma_f16(acc[mi][ni], a[mi], bb[ni]);
        }
        __syncthreads();
    }

    const float s = 1.0f / 128.0f;
    float* pa = PA + (size_t)b * 4096;
#pragma unroll
    for (int mi = 0; mi < 2; mi++) {
        int r0 = wm * 32 + mi * 16 + lr;
#pragma unroll
        for (int ni = 0; ni < 4; ni++) {
            int col = wn * 32 + ni * 8 + lc * 2;
            *(float2*)&pa[r0 * 64 + col] = make_float2(acc[mi][ni][0] * s, acc[mi][ni][1] * s);
            *(float2*)&pa[(r0 + 8) * 64 + col] = make_float2(acc[mi][ni][2] * s, acc[mi][ni][3] * s);
        }
    }
}

// ---------------- colmap: 16-segment parallel build + ordered merge --------
__global__ void build_colmap_seg(const float* __restrict__ pm) {
    int c = blockIdx.x * blockDim.x + threadIdx.x;
    int seg = blockIdx.y;
    if (c >= NCOLS) return;
    int r0 = seg * 268, r1 = r0 + 268;
    if (r1 > NROWS_PM) r1 = NROWS_PM;
    int n = 0;
    for (int r = r0; r < r1; r++) {
        if (pm[(size_t)r * NCOLS + c] != 0.0f) {
            if (n < 8) g_rowsS[(seg * NCOLS + c) * 8 + n] = r;
            n++;
        }
    }
    g_cntS[seg * NCOLS + c] = (n > 8) ? 8 : n;
}
__global__ void merge_colmap() {
    int c = blockIdx.x * blockDim.x + threadIdx.x;
    if (c >= NCOLS) return;
    int n = 0;
    for (int seg = 0; seg < NSEG; seg++) {
        int m = g_cntS[seg * NCOLS + c];
        for (int t = 0; t < m && n < 16; t++)
            g_rows[c * 16 + n++] = g_rowsS[(seg * NCOLS + c) * 8 + t];
    }
    g_cnt[c] = n;
}

// ---------------- g_M partials: split-K x4, deterministic ------------------
__global__ __launch_bounds__(256) void gemm_tn_part(
    const float* __restrict__ A, const float* __restrict__ B) {
    __shared__ float As[8][128];
    __shared__ float Bs[8][128];
    int bi = blockIdx.y, bj = blockIdx.x, ks = blockIdx.z;
    int tid = threadIdx.x;
    int lrow = tid >> 5;
    int lcol = (tid & 31) * 4;
    int tx = tid & 15, ty = tid >> 4;
    int kbase = ks * 256;
    const float* Ap = A + (size_t)(kbase + lrow) * HIDDEN + bi * 128 + lcol;
    const float* Bp = B + (size_t)(kbase + lrow) * HIDDEN + bj * 128 + lcol;
    float acc[8][8];
#pragma unroll
    for (int i = 0; i < 8; i++)
#pragma unroll
        for (int j = 0; j < 8; j++) acc[i][j] = 0.0f;
    for (int k0 = 0; k0 < 256; k0 += 8) {
        *(float4*)&As[lrow][lcol] = *(const float4*)(Ap + (size_t)k0 * HIDDEN);
        *(float4*)&Bs[lrow][lcol] = *(const float4*)(Bp + (size_t)k0 * HIDDEN);
        __syncthreads();
#pragma unroll
        for (int k = 0; k < 8; k++) {
            float a[8], b[8];
            *(float4*)&a[0] = *(float4*)&As[k][ty * 4];
            *(float4*)&a[4] = *(float4*)&As[k][64 + ty * 4];
            *(float4*)&b[0] = *(float4*)&Bs[k][tx * 4];
            *(float4*)&b[4] = *(float4*)&Bs[k][64 + tx * 4];
#pragma unroll
            for (int i = 0; i < 8; i++)
#pragma unroll
                for (int j = 0; j < 8; j++) acc[i][j] += a[i] * b[j];
        }
        __syncthreads();
    }
    float* Mout = g_Mp[ks];
#pragma unroll
    for (int ih = 0; ih < 2; ih++)
#pragma unroll
        for (int i = 0; i < 4; i++) {
            int row = bi * 128 + ih * 64 + ty * 4 + i;
#pragma unroll
            for (int jh = 0; jh < 2; jh++) {
                float4 v = make_float4(acc[ih * 4 + i][jh * 4 + 0], acc[ih * 4 + i][jh * 4 + 1],
                                       acc[ih * 4 + i][jh * 4 + 2], acc[ih * 4 + i][jh * 4 + 3]);
                *(float4*)&Mout[(size_t)row * HIDDEN + bj * 128 + jh * 64 + tx * 4] = v;
            }
        }
}
__global__ __launch_bounds__(256) void mh_combine() {
    int i = blockIdx.x * blockDim.x + threadIdx.x;
    if (i >= HIDDEN * HIDDEN) return;
    float s = g_Mp[0][i] + g_Mp[1][i] + g_Mp[2][i] + g_Mp[3][i];
    g_Mh[i] = __float2half_rn(s);
}

// ---------------- Weff: zero + 48-block partial accumulate -----------------
__global__ void weff_zero() {
    int i = blockIdx.x * blockDim.x + threadIdx.x;
    if (i < 3 * HIDDEN) g_Weff[i] = 0.0f;
}
__global__ void weff_partial(const float* __restrict__ Wpo, const float* __restrict__ Wpk) {
    int i = blockIdx.x;
    int seg = blockIdx.y;
    int tid = threadIdx.x;
    int c0 = seg * 64;
    float acc[4] = {0.f, 0.f, 0.f, 0.f};
    for (int c = c0; c < c0 + 64; c++) {
        float w = Wpo[i * HIDDEN + c];
        const float* row = Wpk + (size_t)c * HIDDEN;
#pragma unroll
        for (int j = 0; j < 4; j++) acc[j] += w * row[j * 256 + tid];
    }
#pragma unroll
    for (int j = 0; j < 4; j++) atomicAdd(&g_Weff[i * HIDDEN + j * 256 + tid], acc[j]);
}

// ---------------- promo offsets (full-precision HS) ------------------------
__global__ void promo_kernel(const float* __restrict__ HS) {
    int b = blockIdx.x;
    int tid = threadIdx.x;
    int lane = tid & 31, w = tid >> 5;
    for (int p = w; p < 24; p += 8) {
        int i = p >> 3;
        int s = p & 7;
        const float* h = HS + ((size_t)b * 64 + 48 + s) * HIDDEN;
        const float* we = g_Weff + i * HIDDEN;
        float acc = 0.f;
        for (int d = lane; d < HIDDEN; d += 32) acc += h[d] * we[d];
#pragma unroll
        for (int o = 16; o; o >>= 1) acc += __shfl_xor_sync(0xFFFFFFFFu, acc, o);
        if (lane == 0) g_PO[b * 24 + i * 8 + s] = acc;
    }
}

// ---------------- final sparse gather --------------------------------------
__global__ void gather_kernel(float* __restrict__ PL, const float* __restrict__ PAfull) {
    int c = blockIdx.x * blockDim.x + threadIdx.x;
    int b = blockIdx.y;
    if (c >= NCOLS) return;
    const float* pa = PAfull + (size_t)b * 4096;
    int n = g_cnt[c];
    float v = 0.f;
    for (int t = 0; t < n; t++) {
        int r = g_rows[c * 16 + t];
        if (r < 4096) {
            v += pa[r] * 0.125f;
        } else {
            int u = r - 4096;
            int r8 = u / 24, rem = u % 24;
            int cc = rem / 3, ii = rem % 3;
            v += pa[(48 + r8) * 64 + 56 + cc] + 8.0f * g_PO[b * 24 + ii * 8 + cc];
        }
    }
    PL[(size_t)b * NCOLS + c] = v;
}

// ---------------- launcher -------------------------------------------------
extern "C" void kernel_launch(void* const* d_in, const int* in_sizes, int n_in,
                              void* d_out, int out_size) {
    const float* HS  = (const float*)d_in[0];
    const float* Wq  = (const float*)d_in[1];
    const float* Wk  = (const float*)d_in[2];
    const float* Wpk = (const float*)d_in[3];
    const float* Wpo = (const float*)d_in[4];
    const float* pm  = (const float*)d_in[5];
    int B = in_sizes[0] / (64 * HIDDEN);

    float* out = (float*)d_out;
    float* PL = out;
    float* PA = out + (size_t)B * NCOLS;

    cudaFuncSetAttribute(pass1_mma, cudaFuncAttributeMaxDynamicSharedMemorySize, P1_SMEMB);

    int n4 = (B * 64 * HIDDEN) / 4;
    preround_hs<<<(n4 + 255) / 256, 256>>>(HS, n4);
    build_colmap_seg<<<dim3((NCOLS + 255) / 256, NSEG), 256>>>(pm);
    merge_colmap<<<(NCOLS + 255) / 256, 256>>>();
    gemm_tn_part<<<dim3(8, 8, 4), 256>>>(Wk, Wq);
    mh_combine<<<(HIDDEN * HIDDEN + 255) / 256, 256>>>();
    weff_zero<<<12, 256>>>();
    weff_partial<<<dim3(3, 16), 256>>>(Wpo, Wpk);
    pass1_mma<<<dim3(4, (B * 64) / 128), 256, P1_SMEMB>>>();
    pass2_mma<<<B, 128>>>(PA);
    promo_kernel<<<B, 256>>>(HS);
    gather_kernel<<<dim3((NCOLS + 255) / 256, B), 256>>>(PL, PA);
}

// round 12
// speedup vs baseline: 2.0644x; 1.0582x over previous
#include <cuda_runtime.h>
#include <cuda_fp16.h>
#include <cstdint>

#define HIDDEN 1024
#define NCOLS 1858
#define NROWS_PM 4288
#define MAXB 2048
#define NSEG 16

// ---------------- scratch (device globals: allocation-free) ----------------
__device__ __half g_HSh[(size_t)MAXB * 64 * HIDDEN]; // HS in fp16
__device__ __half g_Th[(size_t)MAXB * 64 * HIDDEN];  // T = HS @ M in fp16
__device__ __half g_Mh[HIDDEN * HIDDEN];             // M^T in fp16 (n rows, k contiguous)
__device__ float  g_Mp[4][HIDDEN * HIDDEN];          // split-K partials
__device__ float  g_Weff[3 * HIDDEN];
__device__ float  g_PO[MAXB * 24];
__device__ int    g_cnt[NCOLS];
__device__ int    g_rows[NCOLS * 16];
__device__ int    g_cntS[NSEG * NCOLS];
__device__ int    g_rowsS[NSEG * NCOLS * 8];

// ---------------- PTX helpers (arch-agnostic: sm_80+ only) -----------------
__device__ __forceinline__ uint32_t smem_u32(const void* p) {
    uint32_t a;
    asm("{ .reg .u64 t; cvta.to.shared.u64 t, %1; cvt.u32.u64 %0, t; }" : "=r"(a) : "l"(p));
    return a;
}
__device__ __forceinline__ void cp_async16(uint32_t s, const void* g) {
    asm volatile("cp.async.cg.shared.global [%0], [%1], 16;" :: "r"(s), "l"(g));
}
#define CP_COMMIT() asm volatile("cp.async.commit_group;" ::: "memory")
#define CP_WAIT1() asm volatile("cp.async.wait_group 1;" ::: "memory")
#define CP_WAIT0() asm volatile("cp.async.wait_group 0;" ::: "memory")

__device__ __forceinline__ void mma_f16(float* c, const uint32_t* a, const uint32_t* b) {
    asm volatile(
        "mma.sync.aligned.m16n8k16.row.col.f32.f16.f16.f32 "
        "{%0,%1,%2,%3}, {%4,%5,%6,%7}, {%8,%9}, {%0,%1,%2,%3};"
        : "+f"(c[0]), "+f"(c[1]), "+f"(c[2]), "+f"(c[3])
        : "r"(a[0]), "r"(a[1]), "r"(a[2]), "r"(a[3]), "r"(b[0]), "r"(b[1]));
}
__device__ __forceinline__ void ldm_x4(uint32_t* r, uint32_t addr) {
    asm volatile("ldmatrix.sync.aligned.m8n8.x4.shared.b16 {%0,%1,%2,%3}, [%4];"
        : "=r"(r[0]), "=r"(r[1]), "=r"(r[2]), "=r"(r[3]) : "r"(addr));
}
__device__ __forceinline__ uint32_t pack_h2(float x, float y) {
    __half2 h = __floats2half2_rn(x, y);
    return *(uint32_t*)&h;
}
// swizzled byte offset within a [rows x 32half] tile (row stride 64B)
__device__ __forceinline__ uint32_t swz(int row, int ku) {
    return (uint32_t)(row * 64 + ((ku ^ ((row >> 1) & 3)) << 4));
}

// ---------------- preround: HS fp32 -> g_HSh fp16 --------------------------
__global__ __launch_bounds__(256) void preround_hs(const float* __restrict__ HS, int n4) {
    int i = blockIdx.x * blockDim.x + threadIdx.x;
    if (i >= n4) return;
    float4 v = ((const float4*)HS)[i];
    uint2 w;
    w.x = pack_h2(v.x, v.y);
    w.y = pack_h2(v.z, v.w);
    ((uint2*)g_HSh)[i] = w;
}

// ---------------- Pass1: T = HS @ M via fp16 mma + ldmatrix ----------------
// CTA tile 128(M) x 256(N), k-chunk 32, 8 warps (2x4), warp tile 64x64.
// 3-stage cp.async pipeline, ONE barrier per chunk.
#define P1_STAGEB 24576
#define P1_SMEMB (3 * P1_STAGEB)      // 73728 bytes

__global__ __launch_bounds__(256, 1) void pass1_mma() {
    extern __shared__ __half hsm[];
    uint32_t sb = smem_u32(hsm);
    int tid = threadIdx.x, wid = tid >> 5, lane = tid & 31;
    int wm = wid >> 2, wn = wid & 3;
    int lr = lane >> 2, lc = lane & 3;
    int g = lane >> 3, tr = lane & 7;
    int m_base = blockIdx.y * 128;
    int n_base = blockIdx.x * 256;
    const __half* Ag = g_HSh + (size_t)m_base * HIDDEN;

    auto prefetch = [&](int chunk, int stg) {
        int k0 = chunk * 32;
        uint32_t base = sb + stg * P1_STAGEB;
#pragma unroll
        for (int it = 0; it < 2; it++) {                 // A: 512 x 16B
            int idx = tid + it * 256;
            int r = idx >> 2, seg = idx & 3;
            cp_async16(base + swz(r, seg), Ag + (size_t)r * HIDDEN + k0 + seg * 8);
        }
#pragma unroll
        for (int it = 0; it < 4; it++) {                 // B: 1024 x 16B
            int idx = tid + it * 256;
            int r = idx >> 2, seg = idx & 3;
            cp_async16(base + 8192 + swz(r, seg),
                       g_Mh + (size_t)(n_base + r) * HIDDEN + k0 + seg * 8);
        }
    };

    float acc[4][8][4];
#pragma unroll
    for (int i = 0; i < 4; i++)
#pragma unroll
        for (int j = 0; j < 8; j++)
#pragma unroll
            for (int t = 0; t < 4; t++) acc[i][j][t] = 0.0f;

    prefetch(0, 0); CP_COMMIT();
    prefetch(1, 1); CP_COMMIT();

    int stg = 0;
    for (int c = 0; c < 32; c++) {
        if (c < 31) { CP_WAIT1(); } else { CP_WAIT0(); }
        __syncthreads();
        if (c < 30) {
            int ns = stg + 2; if (ns >= 3) ns -= 3;
            prefetch(c + 2, ns);
            CP_COMMIT();
        }
        uint32_t sA = sb + stg * P1_STAGEB;
        uint32_t sB = sA + 8192;
#pragma unroll
        for (int ks = 0; ks < 2; ks++) {
            uint32_t a[4][4], b[8][2];
#pragma unroll
            for (int mi = 0; mi < 4; mi++) {
                int rr = wm * 64 + mi * 16 + ((g & 1) << 3) + tr;
                int ku = ks * 2 + (g >> 1);
                ldm_x4(a[mi], sA + swz(rr, ku));
            }
#pragma unroll
            for (int jj = 0; jj < 8; jj += 2) {
                int rr = wn * 64 + (jj + (g >> 1)) * 8 + tr;
                int ku = ks * 2 + (g & 1);
                uint32_t r4[4];
                ldm_x4(r4, sB + swz(rr, ku));
                b[jj][0] = r4[0]; b[jj][1] = r4[1];
                b[jj + 1][0] = r4[2]; b[jj + 1][1] = r4[3];
            }
#pragma unroll
            for (int mi = 0; mi < 4; mi++)
#pragma unroll
                for (int ni = 0; ni < 8; ni++)
                    mma_f16(acc[mi][ni], a[mi], b[ni]);
        }
        if (++stg == 3) stg = 0;
    }

    // epilogue: store T as fp16
#pragma unroll
    for (int mi = 0; mi < 4; mi++) {
        int r0 = m_base + wm * 64 + mi * 16 + lr;
#pragma unroll
        for (int ni = 0; ni < 8; ni++) {
            int col = n_base + wn * 64 + ni * 8 + lc * 2;
            *(uint32_t*)&g_Th[(size_t)r0 * HIDDEN + col] = pack_h2(acc[mi][ni][0], acc[mi][ni][1]);
            *(uint32_t*)&g_Th[(size_t)(r0 + 8) * HIDDEN + col] = pack_h2(acc[mi][ni][2], acc[mi][ni][3]);
        }
    }
}

// ---------------- Pass2: PA[b] = T[b] @ HS[b]^T / 128 (3-stage) ------------
__global__ __launch_bounds__(128) void pass2_mma(float* __restrict__ PA) {
    __shared__ __half Ts[3][64 * 32];
    __shared__ __half Hs[3][64 * 32];
    int b = blockIdx.x;
    int tid = threadIdx.x, wid = tid >> 5, lane = tid & 31;
    int wm = wid >> 1, wn = wid & 1;
    int lr = lane >> 2, lc = lane & 3;
    int g = lane >> 3, tr = lane & 7;

    const __half* Tg = g_Th + (size_t)b * 64 * HIDDEN;
    const __half* Hg = g_HSh + (size_t)b * 64 * HIDDEN;
    uint32_t sT0 = smem_u32(&Ts[0][0]);
    uint32_t sH0 = smem_u32(&Hs[0][0]);

    auto prefetch = [&](int chunk, int stg) {
        int k0 = chunk * 32;
        uint32_t sT = sT0 + stg * 4096;
        uint32_t sH = sH0 + stg * 4096;
#pragma unroll
        for (int it = 0; it < 2; it++) {
            int idx = tid + it * 128;
            int r = idx >> 2, seg = idx & 3;
            cp_async16(sT + swz(r, seg), Tg + (size_t)r * HIDDEN + k0 + seg * 8);
            cp_async16(sH + swz(r, seg), Hg + (size_t)r * HIDDEN + k0 + seg * 8);
        }
    };

    float acc[2][4][4];
#pragma unroll
    for (int i = 0; i < 2; i++)
#pragma unroll
        for (int j = 0; j < 4; j++)
#pragma unroll
            for (int t = 0; t < 4; t++) acc[i][j][t] = 0.0f;

    prefetch(0, 0); CP_COMMIT();
    prefetch(1, 1); CP_COMMIT();

    int stg = 0;
    for (int c = 0; c < 32; c++) {
        if (c < 31) { CP_WAIT1(); } else { CP_WAIT0(); }
        __syncthreads();
        if (c < 30) {
            int ns = stg + 2; if (ns >= 3) ns -= 3;
            prefetch(c + 2, ns);
            CP_COMMIT();
        }
        uint32_t sT = sT0 + stg * 4096;
        uint32_t sH = sH0 + stg * 4096;
#pragma unroll
        for (int ks = 0; ks < 2; ks++) {
            uint32_t a[2][4], bb[4][2];
#pragma unroll
            for (int mi = 0; mi < 2; mi++) {
                int rr = wm * 32 + mi * 16 + ((g & 1) << 3) + tr;
                int ku = ks * 2 + (g >> 1);
                ldm_x4(a[mi], sT + swz(rr, ku));
            }
#pragma unroll
            for (int jj = 0; jj < 4; jj += 2) {
                int rr = wn * 32 + (jj + (g >> 1)) * 8 + tr;
                int ku = ks * 2 + (g & 1);
                uint32_t r4[4];
                ldm_x4(r4, sH + swz(rr, ku));
                bb[jj][0] = r4[0]; bb[jj][1] = r4[1];
                bb[jj + 1][0] = r4[2]; bb[jj + 1][1] = r4[3];
            }
#pragma unroll
            for (int mi = 0; mi < 2; mi++)
#pragma unroll
                for (int ni = 0; ni < 4; ni++)
                    mma_f16(acc[mi][ni], a[mi], bb[ni]);
        }
        if (++stg == 3) stg = 0;
    }

    const float s = 1.0f / 128.0f;
    float* pa = PA + (size_t)b * 4096;
#pragma unroll
    for (int mi = 0; mi < 2; mi++) {
        int r0 = wm * 32 + mi * 16 + lr;
#pragma unroll
        for (int ni = 0; ni < 4; ni++) {
            int col = wn * 32 + ni * 8 + lc * 2;
            *(float2*)&pa[r0 * 64 + col] = make_float2(acc[mi][ni][0] * s, acc[mi][ni][1] * s);
            *(float2*)&pa[(r0 + 8) * 64 + col] = make_float2(acc[mi][ni][2] * s, acc[mi][ni][3] * s);
        }
    }
}

// ---------------- colmap: 16-segment parallel build + ordered merge --------
__global__ void build_colmap_seg(const float* __restrict__ pm) {
    int c = blockIdx.x * blockDim.x + threadIdx.x;
    int seg = blockIdx.y;
    if (c >= NCOLS) return;
    int r0 = seg * 268, r1 = r0 + 268;
    if (r1 > NROWS_PM) r1 = NROWS_PM;
    int n = 0;
    for (int r = r0; r < r1; r++) {
        if (pm[(size_t)r * NCOLS + c] != 0.0f) {
            if (n < 8) g_rowsS[(seg * NCOLS + c) * 8 + n] = r;
            n++;
        }
    }
    g_cntS[seg * NCOLS + c] = (n > 8) ? 8 : n;
}
__global__ void merge_colmap() {
    int c = blockIdx.x * blockDim.x + threadIdx.x;
    if (c >= NCOLS) return;
    int n = 0;
    for (int seg = 0; seg < NSEG; seg++) {
        int m = g_cntS[seg * NCOLS + c];
        for (int t = 0; t < m && n < 16; t++)
            g_rows[c * 16 + n++] = g_rowsS[(seg * NCOLS + c) * 8 + t];
    }
    g_cnt[c] = n;
}

// ---------------- g_M partials: split-K x4, deterministic ------------------
__global__ __launch_bounds__(256) void gemm_tn_part(
    const float* __restrict__ A, const float* __restrict__ B) {
    __shared__ float As[8][128];
    __shared__ float Bs[8][128];
    int bi = blockIdx.y, bj = blockIdx.x, ks = blockIdx.z;
    int tid = threadIdx.x;
    int lrow = tid >> 5;
    int lcol = (tid & 31) * 4;
    int tx = tid & 15, ty = tid >> 4;
    int kbase = ks * 256;
    const float* Ap = A + (size_t)(kbase + lrow) * HIDDEN + bi * 128 + lcol;
    const float* Bp = B + (size_t)(kbase + lrow) * HIDDEN + bj * 128 + lcol;
    float acc[8][8];
#pragma unroll
    for (int i = 0; i < 8; i++)
#pragma unroll
        for (int j = 0; j < 8; j++) acc[i][j] = 0.0f;
    for (int k0 = 0; k0 < 256; k0 += 8) {
        *(float4*)&As[lrow][lcol] = *(const float4*)(Ap + (size_t)k0 * HIDDEN);
        *(float4*)&Bs[lrow][lcol] = *(const float4*)(Bp + (size_t)k0 * HIDDEN);
        __syncthreads();
#pragma unroll
        for (int k = 0; k < 8; k++) {
            float a[8], b[8];
            *(float4*)&a[0] = *(float4*)&As[k][ty * 4];
            *(float4*)&a[4] = *(float4*)&As[k][64 + ty * 4];
            *(float4*)&b[0] = *(float4*)&Bs[k][tx * 4];
            *(float4*)&b[4] = *(float4*)&Bs[k][64 + tx * 4];
#pragma unroll
            for (int i = 0; i < 8; i++)
#pragma unroll
                for (int j = 0; j < 8; j++) acc[i][j] += a[i] * b[j];
        }
        __syncthreads();
    }
    float* Mout = g_Mp[ks];
#pragma unroll
    for (int ih = 0; ih < 2; ih++)
#pragma unroll
        for (int i = 0; i < 4; i++) {
            int row = bi * 128 + ih * 64 + ty * 4 + i;
#pragma unroll
            for (int jh = 0; jh < 2; jh++) {
                float4 v = make_float4(acc[ih * 4 + i][jh * 4 + 0], acc[ih * 4 + i][jh * 4 + 1],
                                       acc[ih * 4 + i][jh * 4 + 2], acc[ih * 4 + i][jh * 4 + 3]);
                *(float4*)&Mout[(size_t)row * HIDDEN + bj * 128 + jh * 64 + tx * 4] = v;
            }
        }
}
__global__ __launch_bounds__(256) void mh_combine() {
    int i = blockIdx.x * blockDim.x + threadIdx.x;
    if (i >= HIDDEN * HIDDEN) return;
    float s = g_Mp[0][i] + g_Mp[1][i] + g_Mp[2][i] + g_Mp[3][i];
    g_Mh[i] = __float2half_rn(s);
}

// ---------------- Weff: zero + 48-block partial accumulate -----------------
__global__ void weff_zero() {
    int i = blockIdx.x * blockDim.x + threadIdx.x;
    if (i < 3 * HIDDEN) g_Weff[i] = 0.0f;
}
__global__ void weff_partial(const float* __restrict__ Wpo, const float* __restrict__ Wpk) {
    int i = blockIdx.x;
    int seg = blockIdx.y;
    int tid = threadIdx.x;
    int c0 = seg * 64;
    float acc[4] = {0.f, 0.f, 0.f, 0.f};
    for (int c = c0; c < c0 + 64; c++) {
        float w = Wpo[i * HIDDEN + c];
        const float* row = Wpk + (size_t)c * HIDDEN;
#pragma unroll
        for (int j = 0; j < 4; j++) acc[j] += w * row[j * 256 + tid];
    }
#pragma unroll
    for (int j = 0; j < 4; j++) atomicAdd(&g_Weff[i * HIDDEN + j * 256 + tid], acc[j]);
}

// ---------------- promo offsets (full-precision HS) ------------------------
__global__ void promo_kernel(const float* __restrict__ HS) {
    int b = blockIdx.x;
    int tid = threadIdx.x;
    int lane = tid & 31, w = tid >> 5;
    for (int p = w; p < 24; p += 8) {
        int i = p >> 3;
        int s = p & 7;
        const float* h = HS + ((size_t)b * 64 + 48 + s) * HIDDEN;
        const float* we = g_Weff + i * HIDDEN;
        float acc = 0.f;
        for (int d = lane; d < HIDDEN; d += 32) acc += h[d] * we[d];
#pragma unroll
        for (int o = 16; o; o >>= 1) acc += __shfl_xor_sync(0xFFFFFFFFu, acc, o);
        if (lane == 0) g_PO[b * 24 + i * 8 + s] = acc;
    }
}

// ---------------- final sparse gather --------------------------------------
__global__ void gather_kernel(float* __restrict__ PL, const float* __restrict__ PAfull) {
    int c = blockIdx.x * blockDim.x + threadIdx.x;
    int b = blockIdx.y;
    if (c >= NCOLS) return;
    const float* pa = PAfull + (size_t)b * 4096;
    int n = g_cnt[c];
    float v = 0.f;
    for (int t = 0; t < n; t++) {
        int r = g_rows[c * 16 + t];
        if (r < 4096) {
            v += pa[r] * 0.125f;
        } else {
            int u = r - 4096;
            int r8 = u / 24, rem = u % 24;
            int cc = rem / 3, ii = rem % 3;
            v += pa[(48 + r8) * 64 + 56 + cc] + 8.0f * g_PO[b * 24 + ii * 8 + cc];
        }
    }
    PL[(size_t)b * NCOLS + c] = v;
}

// ---------------- launcher (fork/join stream graph) ------------------------
extern "C" void kernel_launch(void* const* d_in, const int* in_sizes, int n_in,
                              void* d_out, int out_size) {
    const float* HS  = (const float*)d_in[0];
    const float* Wq  = (const float*)d_in[1];
    const float* Wk  = (const float*)d_in[2];
    const float* Wpk = (const float*)d_in[3];
    const float* Wpo = (const float*)d_in[4];
    const float* pm  = (const float*)d_in[5];
    int B = in_sizes[0] / (64 * HIDDEN);

    float* out = (float*)d_out;
    float* PL = out;
    float* PA = out + (size_t)B * NCOLS;

    // one-time resources (identical work on every call)
    static cudaStream_t s1 = nullptr, s2 = nullptr, s3 = nullptr;
    static cudaEvent_t e0 = nullptr, ev1 = nullptr, ev2 = nullptr, ev3 = nullptr;
    if (!s1) {
        cudaStreamCreateWithFlags(&s1, cudaStreamNonBlocking);
        cudaStreamCreateWithFlags(&s2, cudaStreamNonBlocking);
        cudaStreamCreateWithFlags(&s3, cudaStreamNonBlocking);
        cudaEventCreateWithFlags(&e0, cudaEventDisableTiming);
        cudaEventCreateWithFlags(&ev1, cudaEventDisableTiming);
        cudaEventCreateWithFlags(&ev2, cudaEventDisableTiming);
        cudaEventCreateWithFlags(&ev3, cudaEventDisableTiming);
        cudaFuncSetAttribute(pass1_mma, cudaFuncAttributeMaxDynamicSharedMemorySize, P1_SMEMB);
    }

    // fork
    cudaEventRecord(e0, 0);
    cudaStreamWaitEvent(s1, e0, 0);
    cudaStreamWaitEvent(s2, e0, 0);
    cudaStreamWaitEvent(s3, e0, 0);

    // s1: colmap
    build_colmap_seg<<<dim3((NCOLS + 255) / 256, NSEG), 256, 0, s1>>>(pm);
    merge_colmap<<<(NCOLS + 255) / 256, 256, 0, s1>>>();
    cudaEventRecord(ev1, s1);

    // s2: M = Wk^T Wq -> fp16
    gemm_tn_part<<<dim3(8, 8, 4), 256, 0, s2>>>(Wk, Wq);
    mh_combine<<<(HIDDEN * HIDDEN + 255) / 256, 256, 0, s2>>>();
    cudaEventRecord(ev2, s2);

    // s3: weff + promo
    weff_zero<<<12, 256, 0, s3>>>();
    weff_partial<<<dim3(3, 16), 256, 0, s3>>>(Wpo, Wpk);
    promo_kernel<<<B, 256, 0, s3>>>(HS);
    cudaEventRecord(ev3, s3);

    // main stream: preround (pass1 needs g_HSh and g_Mh)
    int n4 = (B * 64 * HIDDEN) / 4;
    preround_hs<<<(n4 + 255) / 256, 256>>>(HS, n4);
    cudaStreamWaitEvent(0, ev2, 0);
    pass1_mma<<<dim3(4, (B * 64) / 128), 256, P1_SMEMB>>>();
    pass2_mma<<<B, 128>>>(PA);

    // join colmap + promo before gather
    cudaStreamWaitEvent(0, ev1, 0);
    cudaStreamWaitEvent(0, ev3, 0);
    gather_kernel<<<dim3((NCOLS + 255) / 256, B), 256>>>(PL, PA);
}

// round 14
// speedup vs baseline: 2.1596x; 1.0461x over previous
#include <cuda_runtime.h>
#include <cuda_fp16.h>
#include <cstdint>

#define HIDDEN 1024
#define NCOLS 1858
#define NROWS_PM 4288
#define MAXB 2048
#define NSEG 16

// ---------------- scratch (device globals: allocation-free) ----------------
__device__ __half g_HSh[(size_t)MAXB * 64 * HIDDEN]; // HS in fp16
__device__ __half g_Mh[HIDDEN * HIDDEN];             // M^T in fp16 (n rows, k contiguous)
__device__ float  g_Mp[4][HIDDEN * HIDDEN];          // split-K partials for M
__device__ float  g_PAp[4][(size_t)MAXB * 4096];     // PA partials per n-split
__device__ float  g_Weff[3 * HIDDEN];
__device__ float  g_PO[MAXB * 24];
__device__ int    g_cnt[NCOLS];
__device__ int    g_rows[NCOLS * 16];
__device__ int    g_cntS[NSEG * NCOLS];
__device__ int    g_rowsS[NSEG * NCOLS * 8];

// ---------------- PTX helpers (arch-agnostic: sm_80+ only) -----------------
__device__ __forceinline__ uint32_t smem_u32(const void* p) {
    uint32_t a;
    asm("{ .reg .u64 t; cvta.to.shared.u64 t, %1; cvt.u32.u64 %0, t; }" : "=r"(a) : "l"(p));
    return a;
}
__device__ __forceinline__ void cp_async16(uint32_t s, const void* g) {
    asm volatile("cp.async.cg.shared.global [%0], [%1], 16;" :: "r"(s), "l"(g));
}
#define CP_COMMIT() asm volatile("cp.async.commit_group;" ::: "memory")
#define CP_WAIT1() asm volatile("cp.async.wait_group 1;" ::: "memory")
#define CP_WAIT0() asm volatile("cp.async.wait_group 0;" ::: "memory")

__device__ __forceinline__ void mma_f16(float* c, const uint32_t* a, const uint32_t* b) {
    asm volatile(
        "mma.sync.aligned.m16n8k16.row.col.f32.f16.f16.f32 "
        "{%0,%1,%2,%3}, {%4,%5,%6,%7}, {%8,%9}, {%0,%1,%2,%3};"
        : "+f"(c[0]), "+f"(c[1]), "+f"(c[2]), "+f"(c[3])
        : "r"(a[0]), "r"(a[1]), "r"(a[2]), "r"(a[3]), "r"(b[0]), "r"(b[1]));
}
__device__ __forceinline__ void ldm_x4(uint32_t* r, uint32_t addr) {
    asm volatile("ldmatrix.sync.aligned.m8n8.x4.shared.b16 {%0,%1,%2,%3}, [%4];"
        : "=r"(r[0]), "=r"(r[1]), "=r"(r[2]), "=r"(r[3]) : "r"(addr));
}
__device__ __forceinline__ uint32_t pack_h2(float x, float y) {
    __half2 h = __floats2half2_rn(x, y);
    return *(uint32_t*)&h;
}
// swizzled byte offset within a [rows x 32half] tile (row stride 64B)
__device__ __forceinline__ uint32_t swz(int row, int ku) {
    return (uint32_t)(row * 64 + ((ku ^ ((row >> 1) & 3)) << 4));
}

// ---------------- preround segment: HS fp32 -> g_HSh fp16 ------------------
__global__ __launch_bounds__(256) void preround_hs(const float* __restrict__ HS,
                                                   int base4, int n4) {
    int i = blockIdx.x * blockDim.x + threadIdx.x;
    if (i >= n4) return;
    int gi = base4 + i;
    float4 v = ((const float4*)HS)[gi];
    uint2 w;
    w.x = pack_h2(v.x, v.y);
    w.y = pack_h2(v.z, v.w);
    ((uint2*)g_HSh)[gi] = w;
}

// ---------------- Fused pass1+pass2 ----------------------------------------
// Mainloop: T_tile(128x256) = HS(128rows x1024) @ M[:, n_range], 3-stage pipe.
// Epilogue: stage T_tile->smem (fp16), MMA2: PA_partial += T_tile @ HSn^T.
#define P1_STAGEB 24576
#define HSN_B 73728
#define TST_B 141312
#define P1_SMEMB 208896

__global__ __launch_bounds__(256, 1) void pass1_mma(int m_off) {
    extern __shared__ __half hsm[];
    uint32_t sb = smem_u32(hsm);
    int tid = threadIdx.x, wid = tid >> 5, lane = tid & 31;
    int wm = wid >> 2, wn = wid & 3;
    int lr = lane >> 2, lc = lane & 3;
    int g = lane >> 3, tr = lane & 7;
    int mby = m_off + blockIdx.y;
    int m_base = mby * 128;
    int n_base = blockIdx.x * 256;
    const __half* Ag = g_HSh + (size_t)m_base * HIDDEN;

    // HSn tile: this CTA's 128 rows x 256 n-cols of g_HSh (own cp.async group)
#pragma unroll
    for (int it = 0; it < 16; it++) {
        int idx = tid + it * 256;
        int row = idx >> 5, seg = idx & 31;
        cp_async16(sb + HSN_B + row * 528 + seg * 16,
                   Ag + (size_t)row * HIDDEN + n_base + seg * 8);
    }
    CP_COMMIT();

    auto prefetch = [&](int chunk, int stg) {
        int k0 = chunk * 32;
        uint32_t base = sb + stg * P1_STAGEB;
#pragma unroll
        for (int it = 0; it < 2; it++) {                 // A: 512 x 16B
            int idx = tid + it * 256;
            int r = idx >> 2, seg = idx & 3;
            cp_async16(base + swz(r, seg), Ag + (size_t)r * HIDDEN + k0 + seg * 8);
        }
#pragma unroll
        for (int it = 0; it < 4; it++) {                 // B: 1024 x 16B
            int idx = tid + it * 256;
            int r = idx >> 2, seg = idx & 3;
            cp_async16(base + 8192 + swz(r, seg),
                       g_Mh + (size_t)(n_base + r) * HIDDEN + k0 + seg * 8);
        }
    };

    float acc[4][8][4];
#pragma unroll
    for (int i = 0; i < 4; i++)
#pragma unroll
        for (int j = 0; j < 8; j++)
#pragma unroll
            for (int t = 0; t < 4; t++) acc[i][j][t] = 0.0f;

    prefetch(0, 0); CP_COMMIT();
    prefetch(1, 1); CP_COMMIT();

    int stg = 0;
    for (int c = 0; c < 32; c++) {
        if (c < 31) { CP_WAIT1(); } else { CP_WAIT0(); }
        __syncthreads();
        if (c < 30) {
            int ns = stg + 2; if (ns >= 3) ns -= 3;
            prefetch(c + 2, ns);
            CP_COMMIT();
        }
        uint32_t sA = sb + stg * P1_STAGEB;
        uint32_t sB = sA + 8192;
#pragma unroll
        for (int ks = 0; ks < 2; ks++) {
            uint32_t a[4][4], b[8][2];
#pragma unroll
            for (int mi = 0; mi < 4; mi++) {
                int rr = wm * 64 + mi * 16 + ((g & 1) << 3) + tr;
                int ku = ks * 2 + (g >> 1);
                ldm_x4(a[mi], sA + swz(rr, ku));
            }
#pragma unroll
            for (int jj = 0; jj < 8; jj += 2) {
                int rr = wn * 64 + (jj + (g >> 1)) * 8 + tr;
                int ku = ks * 2 + (g & 1);
                uint32_t r4[4];
                ldm_x4(r4, sB + swz(rr, ku));
                b[jj][0] = r4[0]; b[jj][1] = r4[1];
                b[jj + 1][0] = r4[2]; b[jj + 1][1] = r4[3];
            }
#pragma unroll
            for (int mi = 0; mi < 4; mi++)
#pragma unroll
                for (int ni = 0; ni < 8; ni++)
                    mma_f16(acc[mi][ni], a[mi], b[ni]);
        }
        if (++stg == 3) stg = 0;
    }

    // stage T_tile -> smem (fp16, 528B row stride)
#pragma unroll
    for (int mi = 0; mi < 4; mi++) {
        int r0 = wm * 64 + mi * 16 + lr;
#pragma unroll
        for (int ni = 0; ni < 8; ni++) {
            int col = wn * 64 + ni * 8 + lc * 2;
            *(uint32_t*)((char*)hsm + TST_B + r0 * 528 + col * 2) =
                pack_h2(acc[mi][ni][0], acc[mi][ni][1]);
            *(uint32_t*)((char*)hsm + TST_B + (r0 + 8) * 528 + col * 2) =
                pack_h2(acc[mi][ni][2], acc[mi][ni][3]);
        }
    }
    __syncthreads();

    // MMA2: per board (2/CTA), PA_partial(64x64) = T_board(64x256) @ HSn_board^T
    int wb = wid >> 2;
    int wq = wid & 3;
    int wy = wq >> 1, wx = wq & 1;
    float acc2[2][4][4];
#pragma unroll
    for (int i = 0; i < 2; i++)
#pragma unroll
        for (int j = 0; j < 4; j++)
#pragma unroll
            for (int t = 0; t < 4; t++) acc2[i][j][t] = 0.0f;

#pragma unroll
    for (int k2 = 0; k2 < 16; k2++) {
        uint32_t a2[2][4], b2[4][2];
#pragma unroll
        for (int mi = 0; mi < 2; mi++) {
            int rr = wb * 64 + wy * 32 + mi * 16 + ((g & 1) << 3) + tr;
            int ku = k2 * 2 + (g >> 1);
            ldm_x4(a2[mi], sb + TST_B + rr * 528 + ku * 16);
        }
#pragma unroll
        for (int jj = 0; jj < 4; jj += 2) {
            int rr = wb * 64 + wx * 32 + (jj + (g >> 1)) * 8 + tr;
            int ku = k2 * 2 + (g & 1);
            uint32_t r4[4];
            ldm_x4(r4, sb + HSN_B + rr * 528 + ku * 16);
            b2[jj][0] = r4[0]; b2[jj][1] = r4[1];
            b2[jj + 1][0] = r4[2]; b2[jj + 1][1] = r4[3];
        }
#pragma unroll
        for (int mi = 0; mi < 2; mi++)
#pragma unroll
            for (int ni = 0; ni < 4; ni++)
                mma_f16(acc2[mi][ni], a2[mi], b2[ni]);
    }

    int board = mby * 2 + wb;
    float* pap = g_PAp[blockIdx.x] + (size_t)board * 4096;
#pragma unroll
    for (int mi = 0; mi < 2; mi++) {
        int r = wy * 32 + mi * 16 + lr;
#pragma unroll
        for (int ni = 0; ni < 4; ni++) {
            int col = wx * 32 + ni * 8 + lc * 2;
            *(float2*)&pap[r * 64 + col] = make_float2(acc2[mi][ni][0], acc2[mi][ni][1]);
            *(float2*)&pap[(r + 8) * 64 + col] = make_float2(acc2[mi][ni][2], acc2[mi][ni][3]);
        }
    }
}

// ---------------- PA combine: sum 4 n-split partials, scale 1/128 ----------
__global__ __launch_bounds__(256) void pa_combine(float* __restrict__ PA, int nf4) {
    int i = blockIdx.x * blockDim.x + threadIdx.x;
    if (i >= nf4) return;
    const float4 a = ((const float4*)g_PAp[0])[i];
    const float4 b = ((const float4*)g_PAp[1])[i];
    const float4 c = ((const float4*)g_PAp[2])[i];
    const float4 d = ((const float4*)g_PAp[3])[i];
    const float s = 1.0f / 128.0f;
    float4 o;
    o.x = (a.x + b.x + c.x + d.x) * s;
    o.y = (a.y + b.y + c.y + d.y) * s;
    o.z = (a.z + b.z + c.z + d.z) * s;
    o.w = (a.w + b.w + c.w + d.w) * s;
    ((float4*)PA)[i] = o;
}

// ---------------- colmap: 16-segment parallel build + ordered merge --------
__global__ void build_colmap_seg(const float* __restrict__ pm) {
    int c = blockIdx.x * blockDim.x + threadIdx.x;
    int seg = blockIdx.y;
    if (c >= NCOLS) return;
    int r0 = seg * 268, r1 = r0 + 268;
    if (r1 > NROWS_PM) r1 = NROWS_PM;
    int n = 0;
    for (int r = r0; r < r1; r++) {
        if (pm[(size_t)r * NCOLS + c] != 0.0f) {
            if (n < 8) g_rowsS[(seg * NCOLS + c) * 8 + n] = r;
            n++;
        }
    }
    g_cntS[seg * NCOLS + c] = (n > 8) ? 8 : n;
}
__global__ void merge_colmap() {
    int c = blockIdx.x * blockDim.x + threadIdx.x;
    if (c >= NCOLS) return;
    int n = 0;
    for (int seg = 0; seg < NSEG; seg++) {
        int m = g_cntS[seg * NCOLS + c];
        for (int t = 0; t < m && n < 16; t++)
            g_rows[c * 16 + n++] = g_rowsS[(seg * NCOLS + c) * 8 + t];
    }
    g_cnt[c] = n;
}

// ---------------- g_M partials: split-K x4, deterministic ------------------
__global__ __launch_bounds__(256) void gemm_tn_part(
    const float* __restrict__ A, const float* __restrict__ B) {
    __shared__ float As[8][128];
    __shared__ float Bs[8][128];
    int bi = blockIdx.y, bj = blockIdx.x, ks = blockIdx.z;
    int tid = threadIdx.x;
    int lrow = tid >> 5;
    int lcol = (tid & 31) * 4;
    int tx = tid & 15, ty = tid >> 4;
    int kbase = ks * 256;
    const float* Ap = A + (size_t)(kbase + lrow) * HIDDEN + bi * 128 + lcol;
    const float* Bp = B + (size_t)(kbase + lrow) * HIDDEN + bj * 128 + lcol;
    float acc[8][8];
#pragma unroll
    for (int i = 0; i < 8; i++)
#pragma unroll
        for (int j = 0; j < 8; j++) acc[i][j] = 0.0f;
    for (int k0 = 0; k0 < 256; k0 += 8) {
        *(float4*)&As[lrow][lcol] = *(const float4*)(Ap + (size_t)k0 * HIDDEN);
        *(float4*)&Bs[lrow][lcol] = *(const float4*)(Bp + (size_t)k0 * HIDDEN);
        __syncthreads();
#pragma unroll
        for (int k = 0; k < 8; k++) {
            float a[8], b[8];
            *(float4*)&a[0] = *(float4*)&As[k][ty * 4];
            *(float4*)&a[4] = *(float4*)&As[k][64 + ty * 4];
            *(float4*)&b[0] = *(float4*)&Bs[k][tx * 4];
            *(float4*)&b[4] = *(float4*)&Bs[k][64 + tx * 4];
#pragma unroll
            for (int i = 0; i < 8; i++)
#pragma unroll
                for (int j = 0; j < 8; j++) acc[i][j] += a[i] * b[j];
        }
        __syncthreads();
    }
    float* Mout = g_Mp[ks];
#pragma unroll
    for (int ih = 0; ih < 2; ih++)
#pragma unroll
        for (int i = 0; i < 4; i++) {
            int row = bi * 128 + ih * 64 + ty * 4 + i;
#pragma unroll
            for (int jh = 0; jh < 2; jh++) {
                float4 v = make_float4(acc[ih * 4 + i][jh * 4 + 0], acc[ih * 4 + i][jh * 4 + 1],
                                       acc[ih * 4 + i][jh * 4 + 2], acc[ih * 4 + i][jh * 4 + 3]);
                *(float4*)&Mout[(size_t)row * HIDDEN + bj * 128 + jh * 64 + tx * 4] = v;
            }
        }
}
__global__ __launch_bounds__(256) void mh_combine() {
    int i = blockIdx.x * blockDim.x + threadIdx.x;
    if (i >= HIDDEN * HIDDEN) return;
    float s = g_Mp[0][i] + g_Mp[1][i] + g_Mp[2][i] + g_Mp[3][i];
    g_Mh[i] = __float2half_rn(s);
}

// ---------------- Weff: single kernel, no atomics (grid 3x4) ---------------
__global__ void weff_kernel(const float* __restrict__ Wpo, const float* __restrict__ Wpk) {
    int i = blockIdx.x;              // 0..2
    int jseg = blockIdx.y;           // 0..3
    int tid = threadIdx.x;           // 256
    int col = jseg * 256 + tid;
    float acc = 0.0f;
    for (int c = 0; c < HIDDEN; c++)
        acc += Wpo[i * HIDDEN + c] * Wpk[(size_t)c * HIDDEN + col];
    g_Weff[i * HIDDEN + col] = acc;
}

// ---------------- promo offsets (full-precision HS) ------------------------
__global__ void promo_kernel(const float* __restrict__ HS) {
    int b = blockIdx.x;
    int tid = threadIdx.x;
    int lane = tid & 31, w = tid >> 5;
    for (int p = w; p < 24; p += 8) {
        int i = p >> 3;
        int s = p & 7;
        const float* h = HS + ((size_t)b * 64 + 48 + s) * HIDDEN;
        const float* we = g_Weff + i * HIDDEN;
        float acc = 0.f;
        for (int d = lane; d < HIDDEN; d += 32) acc += h[d] * we[d];
#pragma unroll
        for (int o = 16; o; o >>= 1) acc += __shfl_xor_sync(0xFFFFFFFFu, acc, o);
        if (lane == 0) g_PO[b * 24 + i * 8 + s] = acc;
    }
}

// ---------------- final sparse gather --------------------------------------
__global__ void gather_kernel(float* __restrict__ PL, const float* __restrict__ PAfull) {
    int c = blockIdx.x * blockDim.x + threadIdx.x;
    int b = blockIdx.y;
    if (c >= NCOLS) return;
    const float* pa = PAfull + (size_t)b * 4096;
    int n = g_cnt[c];
    float v = 0.f;
    for (int t = 0; t < n; t++) {
        int r = g_rows[c * 16 + t];
        if (r < 4096) {
            v += pa[r] * 0.125f;
        } else {
            int u = r - 4096;
            int r8 = u / 24, rem = u % 24;
            int cc = rem / 3, ii = rem % 3;
            v += pa[(48 + r8) * 64 + 56 + cc] + 8.0f * g_PO[b * 24 + ii * 8 + cc];
        }
    }
    PL[(size_t)b * NCOLS + c] = v;
}

// ---------------- launcher (3 streams, 12 nodes, 5 events) -----------------
extern "C" void kernel_launch(void* const* d_in, const int* in_sizes, int n_in,
                              void* d_out, int out_size) {
    const float* HS  = (const float*)d_in[0];
    const float* Wq  = (const float*)d_in[1];
    const float* Wk  = (const float*)d_in[2];
    const float* Wpk = (const float*)d_in[3];
    const float* Wpo = (const float*)d_in[4];
    const float* pm  = (const float*)d_in[5];
    int B = in_sizes[0] / (64 * HIDDEN);

    float* out = (float*)d_out;
    float* PL = out;
    float* PA = out + (size_t)B * NCOLS;

    static cudaStream_t s1 = nullptr, s2 = nullptr, s3 = nullptr;
    static cudaEvent_t e0 = nullptr, ev1 = nullptr, ev2 = nullptr;
    static cudaEvent_t ph0 = nullptr, ph1 = nullptr;
    if (!s1) {
        cudaStreamCreateWithFlags(&s1, cudaStreamNonBlocking);
        cudaStreamCreateWithFlags(&s2, cudaStreamNonBlocking);
        cudaStreamCreateWithFlags(&s3, cudaStreamNonBlocking);
        cudaEventCreateWithFlags(&e0, cudaEventDisableTiming);
        cudaEventCreateWithFlags(&ev1, cudaEventDisableTiming);
        cudaEventCreateWithFlags(&ev2, cudaEventDisableTiming);
        cudaEventCreateWithFlags(&ph0, cudaEventDisableTiming);
        cudaEventCreateWithFlags(&ph1, cudaEventDisableTiming);
        cudaFuncSetAttribute(pass1_mma, cudaFuncAttributeMaxDynamicSharedMemorySize, P1_SMEMB);
    }

    // fork
    cudaEventRecord(e0, 0);
    cudaStreamWaitEvent(s1, e0, 0);
    cudaStreamWaitEvent(s2, e0, 0);
    cudaStreamWaitEvent(s3, e0, 0);

    // s1: colmap + weff + promo (all consumed only by gather)
    build_colmap_seg<<<dim3((NCOLS + 255) / 256, NSEG), 256, 0, s1>>>(pm);
    merge_colmap<<<(NCOLS + 255) / 256, 256, 0, s1>>>();
    weff_kernel<<<dim3(3, 4), 256, 0, s1>>>(Wpo, Wpk);
    promo_kernel<<<B, 256, 0, s1>>>(HS);
    cudaEventRecord(ev1, s1);

    // s2: M = Wk^T Wq -> fp16
    gemm_tn_part<<<dim3(8, 8, 4), 256, 0, s2>>>(Wk, Wq);
    mh_combine<<<(HIDDEN * HIDDEN + 255) / 256, 256, 0, s2>>>();
    cudaEventRecord(ev2, s2);

    // s3: preround in 2 halves (pipelined against pass1 halves)
    int n4 = (B * 64 * HIDDEN) / 4;
    int n4h = n4 / 2;
    preround_hs<<<(n4h + 255) / 256, 256, 0, s3>>>(HS, 0, n4h);
    cudaEventRecord(ph0, s3);
    preround_hs<<<(n4h + 255) / 256, 256, 0, s3>>>(HS, n4h, n4h);
    cudaEventRecord(ph1, s3);

    // main: fused pass1+pass2 in 2 halves
    int mqh = (B * 64) / 128 / 2;
    cudaStreamWaitEvent(0, ev2, 0);
    cudaStreamWaitEvent(0, ph0, 0);
    pass1_mma<<<dim3(4, mqh), 256, P1_SMEMB>>>(0);
    cudaStreamWaitEvent(0, ph1, 0);
    pass1_mma<<<dim3(4, mqh), 256, P1_SMEMB>>>(mqh);
    pa_combine<<<(B * 1024 + 255) / 256, 256>>>(PA, B * 1024);

    // join colmap/weff/promo before gather
    cudaStreamWaitEvent(0, ev1, 0);
    gather_kernel<<<dim3((NCOLS + 255) / 256, B), 256>>>(PL, PA);
}

// round 15
// speedup vs baseline: 2.2498x; 1.0417x over previous
#include <cuda_runtime.h>
#include <cuda_fp16.h>
#include <cstdint>

#define HIDDEN 1024
#define NCOLS 1858
#define NROWS_PM 4288
#define MAXB 2048
#define NSEG 16

// ---------------- scratch (device globals: allocation-free) ----------------
__device__ __half g_HSh[(size_t)MAXB * 64 * HIDDEN]; // HS in fp16
__device__ __half g_Mh[HIDDEN * HIDDEN];             // M^T in fp16 (n rows, k contiguous)
__device__ float  g_Mp[8][HIDDEN * HIDDEN];          // split-K partials for M
__device__ float  g_Weff[3 * HIDDEN];
__device__ float  g_PO[MAXB * 24];
__device__ int    g_cnt[NCOLS];
__device__ int    g_rows[NCOLS * 16];
__device__ int    g_cntS[NSEG * NCOLS];
__device__ int    g_rowsS[NSEG * NCOLS * 8];

// ---------------- PTX helpers (arch-agnostic: sm_80+ only) -----------------
__device__ __forceinline__ uint32_t smem_u32(const void* p) {
    uint32_t a;
    asm("{ .reg .u64 t; cvta.to.shared.u64 t, %1; cvt.u32.u64 %0, t; }" : "=r"(a) : "l"(p));
    return a;
}
__device__ __forceinline__ void cp_async16(uint32_t s, const void* g) {
    asm volatile("cp.async.cg.shared.global [%0], [%1], 16;" :: "r"(s), "l"(g));
}
#define CP_COMMIT() asm volatile("cp.async.commit_group;" ::: "memory")
#define CP_WAIT1() asm volatile("cp.async.wait_group 1;" ::: "memory")
#define CP_WAIT0() asm volatile("cp.async.wait_group 0;" ::: "memory")

__device__ __forceinline__ void mma_f16(float* c, const uint32_t* a, const uint32_t* b) {
    asm volatile(
        "mma.sync.aligned.m16n8k16.row.col.f32.f16.f16.f32 "
        "{%0,%1,%2,%3}, {%4,%5,%6,%7}, {%8,%9}, {%0,%1,%2,%3};"
        : "+f"(c[0]), "+f"(c[1]), "+f"(c[2]), "+f"(c[3])
        : "r"(a[0]), "r"(a[1]), "r"(a[2]), "r"(a[3]), "r"(b[0]), "r"(b[1]));
}
__device__ __forceinline__ void ldm_x4(uint32_t* r, uint32_t addr) {
    asm volatile("ldmatrix.sync.aligned.m8n8.x4.shared.b16 {%0,%1,%2,%3}, [%4];"
        : "=r"(r[0]), "=r"(r[1]), "=r"(r[2]), "=r"(r[3]) : "r"(addr));
}
__device__ __forceinline__ uint32_t pack_h2(float x, float y) {
    __half2 h = __floats2half2_rn(x, y);
    return *(uint32_t*)&h;
}
// swizzled byte offset within a [rows x 32half] tile (row stride 64B)
__device__ __forceinline__ uint32_t swz(int row, int ku) {
    return (uint32_t)(row * 64 + ((ku ^ ((row >> 1) & 3)) << 4));
}

// ---------------- preround segment: HS fp32 -> g_HSh fp16 ------------------
__global__ __launch_bounds__(256) void preround_hs(const float* __restrict__ HS,
                                                   int base4, int n4) {
    int i = blockIdx.x * blockDim.x + threadIdx.x;
    if (i >= n4) return;
    int gi = base4 + i;
    float4 v = ((const float4*)HS)[gi];
    uint2 w;
    w.x = pack_h2(v.x, v.y);
    w.y = pack_h2(v.z, v.w);
    ((uint2*)g_HSh)[gi] = w;
}

// ---------------- Fused pass1+pass2, n-split as inner loop -----------------
// CTA = 128 m-rows (2 boards). For split s in 0..3 (n_base = s*256):
//   MMA1: T_tile(128x256) = HS @ M[:, n_range] (3-stage cp.async pipeline)
//   stage T_tile->smem fp16; MMA2: acc2 += T_tile @ HSn^T (register accum
//   across splits, fixed order -> deterministic). Write PA once, scaled.
#define P1_STAGEB 24576
#define HSN_B 73728
#define TST_B 141312
#define P1_SMEMB 208896

__global__ __launch_bounds__(256, 1) void pass1_mma(float* __restrict__ PA, int m_off) {
    extern __shared__ __half hsm[];
    uint32_t sb = smem_u32(hsm);
    int tid = threadIdx.x, wid = tid >> 5, lane = tid & 31;
    int wm = wid >> 2, wn = wid & 3;
    int lr = lane >> 2, lc = lane & 3;
    int g = lane >> 3, tr = lane & 7;
    int mby = m_off + blockIdx.x;
    int m_base = mby * 128;
    const __half* Ag = g_HSh + (size_t)m_base * HIDDEN;

    // MMA2 decomposition: board wb (2/CTA), 2x2 warp grid per board
    int wb = wid >> 2;
    int wq = wid & 3;
    int wy = wq >> 1, wx = wq & 1;
    float acc2[2][4][4];
#pragma unroll
    for (int i = 0; i < 2; i++)
#pragma unroll
        for (int j = 0; j < 4; j++)
#pragma unroll
            for (int t = 0; t < 4; t++) acc2[i][j][t] = 0.0f;

    for (int s = 0; s < 4; s++) {
        int n_base = s * 256;
        if (s > 0) __syncthreads();   // prior split's MMA2 done with HSn/Tst

        // HSn tile: 128 rows x 256 n-cols of this CTA's HS rows
#pragma unroll
        for (int it = 0; it < 16; it++) {
            int idx = tid + it * 256;
            int row = idx >> 5, seg = idx & 31;
            cp_async16(sb + HSN_B + row * 528 + seg * 16,
                       Ag + (size_t)row * HIDDEN + n_base + seg * 8);
        }
        CP_COMMIT();

        auto prefetch = [&](int chunk, int stg) {
            int k0 = chunk * 32;
            uint32_t base = sb + stg * P1_STAGEB;
#pragma unroll
            for (int it = 0; it < 2; it++) {             // A: 512 x 16B
                int idx = tid + it * 256;
                int r = idx >> 2, seg = idx & 3;
                cp_async16(base + swz(r, seg), Ag + (size_t)r * HIDDEN + k0 + seg * 8);
            }
#pragma unroll
            for (int it = 0; it < 4; it++) {             // B: 1024 x 16B
                int idx = tid + it * 256;
                int r = idx >> 2, seg = idx & 3;
                cp_async16(base + 8192 + swz(r, seg),
                           g_Mh + (size_t)(n_base + r) * HIDDEN + k0 + seg * 8);
            }
        };

        float acc[4][8][4];
#pragma unroll
        for (int i = 0; i < 4; i++)
#pragma unroll
            for (int j = 0; j < 8; j++)
#pragma unroll
                for (int t = 0; t < 4; t++) acc[i][j][t] = 0.0f;

        prefetch(0, 0); CP_COMMIT();
        prefetch(1, 1); CP_COMMIT();

        int stg = 0;
        for (int c = 0; c < 32; c++) {
            if (c < 31) { CP_WAIT1(); } else { CP_WAIT0(); }
            __syncthreads();
            if (c < 30) {
                int ns = stg + 2; if (ns >= 3) ns -= 3;
                prefetch(c + 2, ns);
                CP_COMMIT();
            }
            uint32_t sA = sb + stg * P1_STAGEB;
            uint32_t sB = sA + 8192;
#pragma unroll
            for (int ks = 0; ks < 2; ks++) {
                uint32_t a[4][4], b[8][2];
#pragma unroll
                for (int mi = 0; mi < 4; mi++) {
                    int rr = wm * 64 + mi * 16 + ((g & 1) << 3) + tr;
                    int ku = ks * 2 + (g >> 1);
                    ldm_x4(a[mi], sA + swz(rr, ku));
                }
#pragma unroll
                for (int jj = 0; jj < 8; jj += 2) {
                    int rr = wn * 64 + (jj + (g >> 1)) * 8 + tr;
                    int ku = ks * 2 + (g & 1);
                    uint32_t r4[4];
                    ldm_x4(r4, sB + swz(rr, ku));
                    b[jj][0] = r4[0]; b[jj][1] = r4[1];
                    b[jj + 1][0] = r4[2]; b[jj + 1][1] = r4[3];
                }
#pragma unroll
                for (int mi = 0; mi < 4; mi++)
#pragma unroll
                    for (int ni = 0; ni < 8; ni++)
                        mma_f16(acc[mi][ni], a[mi], b[ni]);
            }
            if (++stg == 3) stg = 0;
        }

        // stage T_tile -> smem (fp16, 528B row stride)
#pragma unroll
        for (int mi = 0; mi < 4; mi++) {
            int r0 = wm * 64 + mi * 16 + lr;
#pragma unroll
            for (int ni = 0; ni < 8; ni++) {
                int col = wn * 64 + ni * 8 + lc * 2;
                *(uint32_t*)((char*)hsm + TST_B + r0 * 528 + col * 2) =
                    pack_h2(acc[mi][ni][0], acc[mi][ni][1]);
                *(uint32_t*)((char*)hsm + TST_B + (r0 + 8) * 528 + col * 2) =
                    pack_h2(acc[mi][ni][2], acc[mi][ni][3]);
            }
        }
        __syncthreads();

        // MMA2 accumulate: PA_board(64x64) += T_board(64x256) @ HSn_board^T
#pragma unroll
        for (int k2 = 0; k2 < 16; k2++) {
            uint32_t a2[2][4], b2[4][2];
#pragma unroll
            for (int mi = 0; mi < 2; mi++) {
                int rr = wb * 64 + wy * 32 + mi * 16 + ((g & 1) << 3) + tr;
                int ku = k2 * 2 + (g >> 1);
                ldm_x4(a2[mi], sb + TST_B + rr * 528 + ku * 16);
            }
#pragma unroll
            for (int jj = 0; jj < 4; jj += 2) {
                int rr = wb * 64 + wx * 32 + (jj + (g >> 1)) * 8 + tr;
                int ku = k2 * 2 + (g & 1);
                uint32_t r4[4];
                ldm_x4(r4, sb + HSN_B + rr * 528 + ku * 16);
                b2[jj][0] = r4[0]; b2[jj][1] = r4[1];
                b2[jj + 1][0] = r4[2]; b2[jj + 1][1] = r4[3];
            }
#pragma unroll
            for (int mi = 0; mi < 2; mi++)
#pragma unroll
                for (int ni = 0; ni < 4; ni++)
                    mma_f16(acc2[mi][ni], a2[mi], b2[ni]);
        }
    }

    // write PA once, scaled by 1/128
    const float sc = 1.0f / 128.0f;
    int board = mby * 2 + wb;
    float* pa = PA + (size_t)board * 4096;
#pragma unroll
    for (int mi = 0; mi < 2; mi++) {
        int r = wy * 32 + mi * 16 + lr;
#pragma unroll
        for (int ni = 0; ni < 4; ni++) {
            int col = wx * 32 + ni * 8 + lc * 2;
            *(float2*)&pa[r * 64 + col] =
                make_float2(acc2[mi][ni][0] * sc, acc2[mi][ni][1] * sc);
            *(float2*)&pa[(r + 8) * 64 + col] =
                make_float2(acc2[mi][ni][2] * sc, acc2[mi][ni][3] * sc);
        }
    }
}

// ---------------- colmap: 16-segment parallel build + ordered merge --------
__global__ void build_colmap_seg(const float* __restrict__ pm) {
    int c = blockIdx.x * blockDim.x + threadIdx.x;
    int seg = blockIdx.y;
    if (c >= NCOLS) return;
    int r0 = seg * 268, r1 = r0 + 268;
    if (r1 > NROWS_PM) r1 = NROWS_PM;
    int n = 0;
    for (int r = r0; r < r1; r++) {
        if (pm[(size_t)r * NCOLS + c] != 0.0f) {
            if (n < 8) g_rowsS[(seg * NCOLS + c) * 8 + n] = r;
            n++;
        }
    }
    g_cntS[seg * NCOLS + c] = (n > 8) ? 8 : n;
}
__global__ void merge_colmap() {
    int c = blockIdx.x * blockDim.x + threadIdx.x;
    if (c >= NCOLS) return;
    int n = 0;
    for (int seg = 0; seg < NSEG; seg++) {
        int m = g_cntS[seg * NCOLS + c];
        for (int t = 0; t < m && n < 16; t++)
            g_rows[c * 16 + n++] = g_rowsS[(seg * NCOLS + c) * 8 + t];
    }
    g_cnt[c] = n;
}

// ---------------- g_M partials: split-K x8, deterministic ------------------
__global__ __launch_bounds__(256) void gemm_tn_part(
    const float* __restrict__ A, const float* __restrict__ B) {
    __shared__ float As[8][128];
    __shared__ float Bs[8][128];
    int bi = blockIdx.y, bj = blockIdx.x, ks = blockIdx.z;
    int tid = threadIdx.x;
    int lrow = tid >> 5;
    int lcol = (tid & 31) * 4;
    int tx = tid & 15, ty = tid >> 4;
    int kbase = ks * 128;
    const float* Ap = A + (size_t)(kbase + lrow) * HIDDEN + bi * 128 + lcol;
    const float* Bp = B + (size_t)(kbase + lrow) * HIDDEN + bj * 128 + lcol;
    float acc[8][8];
#pragma unroll
    for (int i = 0; i < 8; i++)
#pragma unroll
        for (int j = 0; j < 8; j++) acc[i][j] = 0.0f;
    for (int k0 = 0; k0 < 128; k0 += 8) {
        *(float4*)&As[lrow][lcol] = *(const float4*)(Ap + (size_t)k0 * HIDDEN);
        *(float4*)&Bs[lrow][lcol] = *(const float4*)(Bp + (size_t)k0 * HIDDEN);
        __syncthreads();
#pragma unroll
        for (int k = 0; k < 8; k++) {
            float a[8], b[8];
            *(float4*)&a[0] = *(float4*)&As[k][ty * 4];
            *(float4*)&a[4] = *(float4*)&As[k][64 + ty * 4];
            *(float4*)&b[0] = *(float4*)&Bs[k][tx * 4];
            *(float4*)&b[4] = *(float4*)&Bs[k][64 + tx * 4];
#pragma unroll
            for (int i = 0; i < 8; i++)
#pragma unroll
                for (int j = 0; j < 8; j++) acc[i][j] += a[i] * b[j];
        }
        __syncthreads();
    }
    float* Mout = g_Mp[ks];
#pragma unroll
    for (int ih = 0; ih < 2; ih++)
#pragma unroll
        for (int i = 0; i < 4; i++) {
            int row = bi * 128 + ih * 64 + ty * 4 + i;
#pragma unroll
            for (int jh = 0; jh < 2; jh++) {
                float4 v = make_float4(acc[ih * 4 + i][jh * 4 + 0], acc[ih * 4 + i][jh * 4 + 1],
                                       acc[ih * 4 + i][jh * 4 + 2], acc[ih * 4 + i][jh * 4 + 3]);
                *(float4*)&Mout[(size_t)row * HIDDEN + bj * 128 + jh * 64 + tx * 4] = v;
            }
        }
}
__global__ __launch_bounds__(256) void mh_combine() {
    int i = blockIdx.x * blockDim.x + threadIdx.x;
    if (i >= HIDDEN * HIDDEN) return;
    float s = ((g_Mp[0][i] + g_Mp[1][i]) + (g_Mp[2][i] + g_Mp[3][i]))
            + ((g_Mp[4][i] + g_Mp[5][i]) + (g_Mp[6][i] + g_Mp[7][i]));
    g_Mh[i] = __float2half_rn(s);
}

// ---------------- Weff: single kernel, no atomics (grid 3x4) ---------------
__global__ void weff_kernel(const float* __restrict__ Wpo, const float* __restrict__ Wpk) {
    int i = blockIdx.x;
    int jseg = blockIdx.y;
    int tid = threadIdx.x;
    int col = jseg * 256 + tid;
    float acc = 0.0f;
    for (int c = 0; c < HIDDEN; c++)
        acc += Wpo[i * HIDDEN + c] * Wpk[(size_t)c * HIDDEN + col];
    g_Weff[i * HIDDEN + col] = acc;
}

// ---------------- promo offsets (full-precision HS) ------------------------
__global__ void promo_kernel(const float* __restrict__ HS) {
    int b = blockIdx.x;
    int tid = threadIdx.x;
    int lane = tid & 31, w = tid >> 5;
    for (int p = w; p < 24; p += 8) {
        int i = p >> 3;
        int s = p & 7;
        const float* h = HS + ((size_t)b * 64 + 48 + s) * HIDDEN;
        const float* we = g_Weff + i * HIDDEN;
        float acc = 0.f;
        for (int d = lane; d < HIDDEN; d += 32) acc += h[d] * we[d];
#pragma unroll
        for (int o = 16; o; o >>= 1) acc += __shfl_xor_sync(0xFFFFFFFFu, acc, o);
        if (lane == 0) g_PO[b * 24 + i * 8 + s] = acc;
    }
}

// ---------------- final sparse gather --------------------------------------
__global__ void gather_kernel(float* __restrict__ PL, const float* __restrict__ PAfull) {
    int c = blockIdx.x * blockDim.x + threadIdx.x;
    int b = blockIdx.y;
    if (c >= NCOLS) return;
    const float* pa = PAfull + (size_t)b * 4096;
    int n = g_cnt[c];
    float v = 0.f;
    for (int t = 0; t < n; t++) {
        int r = g_rows[c * 16 + t];
        if (r < 4096) {
            v += pa[r] * 0.125f;
        } else {
            int u = r - 4096;
            int r8 = u / 24, rem = u % 24;
            int cc = rem / 3, ii = rem % 3;
            v += pa[(48 + r8) * 64 + 56 + cc] + 8.0f * g_PO[b * 24 + ii * 8 + cc];
        }
    }
    PL[(size_t)b * NCOLS + c] = v;
}

// ---------------- launcher (3 streams, 11 nodes, 5 events) -----------------
extern "C" void kernel_launch(void* const* d_in, const int* in_sizes, int n_in,
                              void* d_out, int out_size) {
    const float* HS  = (const float*)d_in[0];
    const float* Wq  = (const float*)d_in[1];
    const float* Wk  = (const float*)d_in[2];
    const float* Wpk = (const float*)d_in[3];
    const float* Wpo = (const float*)d_in[4];
    const float* pm  = (const float*)d_in[5];
    int B = in_sizes[0] / (64 * HIDDEN);

    float* out = (float*)d_out;
    float* PL = out;
    float* PA = out + (size_t)B * NCOLS;

    static cudaStream_t s1 = nullptr, s2 = nullptr, s3 = nullptr;
    static cudaEvent_t e0 = nullptr, ev1 = nullptr, ev2 = nullptr;
    static cudaEvent_t ph0 = nullptr, ph1 = nullptr;
    if (!s1) {
        cudaStreamCreateWithFlags(&s1, cudaStreamNonBlocking);
        cudaStreamCreateWithFlags(&s2, cudaStreamNonBlocking);
        cudaStreamCreateWithFlags(&s3, cudaStreamNonBlocking);
        cudaEventCreateWithFlags(&e0, cudaEventDisableTiming);
        cudaEventCreateWithFlags(&ev1, cudaEventDisableTiming);
        cudaEventCreateWithFlags(&ev2, cudaEventDisableTiming);
        cudaEventCreateWithFlags(&ph0, cudaEventDisableTiming);
        cudaEventCreateWithFlags(&ph1, cudaEventDisableTiming);
        cudaFuncSetAttribute(pass1_mma, cudaFuncAttributeMaxDynamicSharedMemorySize, P1_SMEMB);
    }

    // fork
    cudaEventRecord(e0, 0);
    cudaStreamWaitEvent(s1, e0, 0);
    cudaStreamWaitEvent(s2, e0, 0);
    cudaStreamWaitEvent(s3, e0, 0);

    // s1: colmap + weff + promo (all consumed only by gather)
    build_colmap_seg<<<dim3((NCOLS + 255) / 256, NSEG), 256, 0, s1>>>(pm);
    merge_colmap<<<(NCOLS + 255) / 256, 256, 0, s1>>>();
    weff_kernel<<<dim3(3, 4), 256, 0, s1>>>(Wpo, Wpk);
    promo_kernel<<<B, 256, 0, s1>>>(HS);
    cudaEventRecord(ev1, s1);

    // s2: M = Wk^T Wq -> fp16 (split-K x8)
    gemm_tn_part<<<dim3(8, 8, 8), 256, 0, s2>>>(Wk, Wq);
    mh_combine<<<(HIDDEN * HIDDEN + 255) / 256, 256, 0, s2>>>();
    cudaEventRecord(ev2, s2);

    // s3: preround, asymmetric split (first = 2 clean waves of pass1)
    int nblk = (B * 64) / 128;
    int blk1 = nblk < 296 ? (nblk + 1) / 2 : 296;
    int blk2 = nblk - blk1;
    int n4_1 = blk1 * 128 * (HIDDEN / 4);
    int n4_2 = blk2 * 128 * (HIDDEN / 4);
    preround_hs<<<(n4_1 + 255) / 256, 256, 0, s3>>>(HS, 0, n4_1);
    cudaEventRecord(ph0, s3);
    if (n4_2 > 0) preround_hs<<<(n4_2 + 255) / 256, 256, 0, s3>>>(HS, n4_1, n4_2);
    cudaEventRecord(ph1, s3);

    // main: fused pass1+pass2 (asymmetric halves), direct PA output
    cudaStreamWaitEvent(0, ev2, 0);
    cudaStreamWaitEvent(0, ph0, 0);
    pass1_mma<<<blk1, 256, P1_SMEMB>>>(PA, 0);
    cudaStreamWaitEvent(0, ph1, 0);
    if (blk2 > 0) pass1_mma<<<blk2, 256, P1_SMEMB>>>(PA, blk1);

    // join colmap/weff/promo before gather
    cudaStreamWaitEvent(0, ev1, 0);
    gather_kernel<<<dim3((NCOLS + 255) / 256, B), 256>>>(PL, PA);
}